// round 5
// baseline (speedup 1.0000x reference)
#include <cuda_runtime.h>
#include <cuda_bf16.h>
#include <math.h>
#include <stdint.h>

#define N_ENTS  100000
#define N_RELS  64
#define EDIM    128
#define KNBR    32
#define BATCH   16384

// ---------------- device-global scratch ------------------------------------------
__device__ float         g_EntN[(size_t)N_ENTS * EDIM];    // fp32 (k_main gathers)
__device__ __nv_bfloat16 g_EntH[(size_t)N_ENTS * EDIM];    // bf16 hi (gemm A)
__device__ __nv_bfloat16 g_EntL[(size_t)N_ENTS * EDIM];    // bf16 lo
__device__ float         g_TrT [(size_t)N_ENTS * EDIM];
__device__ float         g_RelN[(size_t)N_RELS * EDIM];
__device__ __nv_bfloat16 g_WsH[3 * EDIM * EDIM];           // Wr,W1,W2 hi
__device__ __nv_bfloat16 g_WsL[3 * EDIM * EDIM];           // Wr,W1,W2 lo
__device__ __nv_bfloat16 g_X1h[(size_t)BATCH * EDIM];
__device__ __nv_bfloat16 g_X1l[(size_t)BATCH * EDIM];
__device__ __nv_bfloat16 g_X2h[(size_t)BATCH * EDIM];
__device__ __nv_bfloat16 g_X2l[(size_t)BATCH * EDIM];

// ---------------- helpers ----------------------------------------------------------
__device__ __forceinline__ uint32_t smem_u32(const void* p) {
    uint32_t a;
    asm("{ .reg .u64 t; cvta.to.shared.u64 t, %1; cvt.u32.u64 %0, t; }" : "=r"(a) : "l"(p));
    return a;
}
__device__ __forceinline__ void ldmx4(uint32_t& r0, uint32_t& r1, uint32_t& r2, uint32_t& r3,
                                      uint32_t addr) {
    asm volatile("ldmatrix.sync.aligned.m8n8.x4.shared.b16 {%0,%1,%2,%3}, [%4];"
                 : "=r"(r0), "=r"(r1), "=r"(r2), "=r"(r3) : "r"(addr));
}
__device__ __forceinline__ void mma_bf16(float* d, const uint32_t* a, const uint32_t* b) {
    asm volatile(
        "mma.sync.aligned.m16n8k16.row.col.f32.bf16.bf16.f32 "
        "{%0,%1,%2,%3}, {%4,%5,%6,%7}, {%8,%9}, {%0,%1,%2,%3};"
        : "+f"(d[0]), "+f"(d[1]), "+f"(d[2]), "+f"(d[3])
        : "r"(a[0]), "r"(a[1]), "r"(a[2]), "r"(a[3]), "r"(b[0]), "r"(b[1]));
}
__device__ __forceinline__ uint32_t pk_bf2(__nv_bfloat16 a, __nv_bfloat16 b) {
    __nv_bfloat162 t(a, b);
    return *(uint32_t*)&t;
}

// padded bf16 tiles, row stride 136 elems (272 B) -> conflict-free ldmatrix
#define LDT 136
#define A_TILE_B (64  * LDT * 2)   // 17408
#define B_TILE_B (128 * LDT * 2)   // 34816
#define OFF_BIAS 0
#define OFF_AH   512
#define OFF_AL   (512 + A_TILE_B)
#define OFF_BH   (512 + 2 * A_TILE_B)
#define OFF_BL   (512 + 2 * A_TILE_B + B_TILE_B)
#define SMEM_MM  (512 + 2 * A_TILE_B + 2 * B_TILE_B)   // 104960 B -> 2 CTAs/SM

// pure bf16 copy: gmem (row stride 128) -> padded smem (rows >= rows_valid zeroed)
template <int ROWS>
__device__ __forceinline__ void copy_tile(const __nv_bfloat16* __restrict__ src,
                                          int rows_valid, char* sm, int off, int tid) {
    #pragma unroll
    for (int i = 0; i < ROWS * 16 / 256; i++) {
        int g = tid + i * 256;
        int row = g >> 4, c8 = g & 15;
        uint4 v = make_uint4(0u, 0u, 0u, 0u);
        if (row < rows_valid)
            v = *((const uint4*)(src + (size_t)row * EDIM) + c8);
        *(uint4*)(sm + off + (size_t)row * LDT * 2 + c8 * 16) = v;
    }
}

// ---------------- GEMM: C[M,128] = epi(A[M,128] @ B[128,128]^T + bias) -------------
// A, B pre-split into bf16 hi/lo -> prologue is a pure copy. 64x128 CTA tile,
// 256 threads (2x4 warps, 32x32 warp tiles), 2 CTAs/SM.
// MODE 0: store; MODE 1: store leaky; MODE 2: += leaky
template <int MODE>
__global__ __launch_bounds__(256, 2) void k_gemm2(const __nv_bfloat16* __restrict__ Ah,
                                                  const __nv_bfloat16* __restrict__ Al,
                                                  const __nv_bfloat16* __restrict__ Bh,
                                                  const __nv_bfloat16* __restrict__ Bl,
                                                  const float* __restrict__ bias,
                                                  float* __restrict__ C, int M) {
    extern __shared__ char sm[];
    uint32_t smb = smem_u32(sm);
    int tid  = threadIdx.x;
    int wid  = tid >> 5, lane = tid & 31;
    int wy   = wid >> 2, wx = wid & 3;
    int m0   = blockIdx.x * 64;

    if (tid < 128) ((float*)(sm + OFF_BIAS))[tid] = bias[tid];
    copy_tile<64> (Ah + (size_t)m0 * EDIM, M - m0, sm, OFF_AH, tid);
    copy_tile<64> (Al + (size_t)m0 * EDIM, M - m0, sm, OFF_AL, tid);
    copy_tile<128>(Bh, 128, sm, OFF_BH, tid);
    copy_tile<128>(Bl, 128, sm, OFF_BL, tid);
    __syncthreads();

    int rowA  = wy * 32 + (lane & 15);
    int colA  = (lane >> 4) * 8;
    int nrow  = wx * 32 + (lane & 7) + ((lane >> 4) ? 8 : 0);
    int kaddB = ((lane >> 3) & 1) * 8;

    uint32_t aBaseH = smb + OFF_AH, aBaseL = smb + OFF_AL;
    uint32_t bBaseH = smb + OFF_BH, bBaseL = smb + OFF_BL;

    float d[2][4][4];
    #pragma unroll
    for (int i = 0; i < 2; i++)
        #pragma unroll
        for (int j = 0; j < 4; j++)
            #pragma unroll
            for (int q = 0; q < 4; q++) d[i][j][q] = 0.f;

    #pragma unroll
    for (int pass = 0; pass < 3; pass++) {
        uint32_t aB = (pass == 2) ? aBaseL : aBaseH;
        uint32_t bB = (pass == 1) ? bBaseL : bBaseH;
        #pragma unroll
        for (int ks = 0; ks < 8; ks++) {
            int k0 = ks * 16;
            uint32_t a[2][4];
            #pragma unroll
            for (int mi = 0; mi < 2; mi++) {
                uint32_t addr = aB + (uint32_t)(((rowA + mi * 16) * LDT + k0 + colA) * 2);
                ldmx4(a[mi][0], a[mi][1], a[mi][2], a[mi][3], addr);
            }
            uint32_t b[4][2];
            #pragma unroll
            for (int nj2 = 0; nj2 < 2; nj2++) {
                uint32_t addr = bB + (uint32_t)(((nrow + nj2 * 16) * LDT + k0 + kaddB) * 2);
                uint32_t r0, r1, r2, r3;
                ldmx4(r0, r1, r2, r3, addr);
                b[nj2 * 2 + 0][0] = r0; b[nj2 * 2 + 0][1] = r1;
                b[nj2 * 2 + 1][0] = r2; b[nj2 * 2 + 1][1] = r3;
            }
            #pragma unroll
            for (int mi = 0; mi < 2; mi++)
                #pragma unroll
                for (int nj = 0; nj < 4; nj++)
                    mma_bf16(d[mi][nj], a[mi], b[nj]);
        }
    }

    const float* sb = (const float*)(sm + OFF_BIAS);
    int qrow = lane >> 2, qcol = (lane & 3) * 2;
    #pragma unroll
    for (int mi = 0; mi < 2; mi++) {
        #pragma unroll
        for (int half = 0; half < 2; half++) {
            int gm = m0 + wy * 32 + mi * 16 + qrow + half * 8;
            if (gm < M) {
                #pragma unroll
                for (int nj = 0; nj < 4; nj++) {
                    int gc = wx * 32 + nj * 8 + qcol;
                    float x0 = d[mi][nj][half * 2 + 0] + sb[gc];
                    float x1 = d[mi][nj][half * 2 + 1] + sb[gc + 1];
                    if (MODE >= 1) {
                        x0 = (x0 > 0.f) ? x0 : 0.2f * x0;
                        x1 = (x1 > 0.f) ? x1 : 0.2f * x1;
                    }
                    float2* p = (float2*)(C + (size_t)gm * 128 + gc);
                    if (MODE == 2) {
                        float2 c = *p;
                        x0 += c.x;
                        x1 += c.y;
                    }
                    *p = make_float2(x0, x1);
                }
            }
        }
    }
}

// ---------------- K0: split weight matrices into bf16 hi/lo -------------------------
__global__ __launch_bounds__(256) void k_split_w(const float* __restrict__ w0,
                                                 const float* __restrict__ w1,
                                                 const float* __restrict__ w2) {
    int id = blockIdx.y;
    const float* w = (id == 0) ? w0 : (id == 1) ? w1 : w2;
    int i = blockIdx.x * 256 + threadIdx.x;
    float f = w[i];
    __nv_bfloat16 h = __float2bfloat16(f);
    __nv_bfloat16 l = __float2bfloat16(f - __bfloat162float(h));
    g_WsH[id * EDIM * EDIM + i] = h;
    g_WsL[id * EDIM * EDIM + i] = l;
}

// ---------------- K1: row max-norm (+ bf16 hi/lo for ent) ---------------------------
__global__ __launch_bounds__(256) void k_normalize(const float* __restrict__ ent,
                                                   const float* __restrict__ rel) {
    int row = blockIdx.x * 8 + (threadIdx.x >> 5);
    int l   = threadIdx.x & 31;
    bool is_ent = (row < N_ENTS);
    const float* src;
    float* dst;
    if (is_ent) {
        src = ent + (size_t)row * EDIM;
        dst = g_EntN + (size_t)row * EDIM;
    } else {
        int r = row - N_ENTS;
        if (r >= N_RELS) return;
        src = rel + (size_t)r * EDIM;
        dst = g_RelN + (size_t)r * EDIM;
    }
    float4 v = ((const float4*)src)[l];
    float ss = v.x * v.x + v.y * v.y + v.z * v.z + v.w * v.w;
    #pragma unroll
    for (int o = 16; o; o >>= 1) ss += __shfl_xor_sync(0xffffffffu, ss, o);
    float n = sqrtf(ss);
    float s = fminf(1.0f, 1.0f / fmaxf(n, 1e-12f));
    float f[4] = {v.x * s, v.y * s, v.z * s, v.w * s};
    ((float4*)dst)[l] = make_float4(f[0], f[1], f[2], f[3]);
    if (is_ent) {
        __nv_bfloat16 h[4], lo[4];
        #pragma unroll
        for (int j = 0; j < 4; j++) {
            h[j]  = __float2bfloat16(f[j]);
            lo[j] = __float2bfloat16(f[j] - __bfloat162float(h[j]));
        }
        size_t o = (size_t)row * EDIM + l * 4;
        *(uint2*)(g_EntH + o) = make_uint2(pk_bf2(h[0], h[1]), pk_bf2(h[2], h[3]));
        *(uint2*)(g_EntL + o) = make_uint2(pk_bf2(lo[0], lo[1]), pk_bf2(lo[2], lo[3]));
    }
}

// ---------------- K3: attention + aggregation ---------------------------------------
__global__ __launch_bounds__(128) void k_main(const int* __restrict__ idx,
                                              const int* __restrict__ adj_ent,
                                              const int* __restrict__ adj_rel) {
    __shared__ __align__(16) float s_hr[128];
    __shared__ __align__(16) float s_h[128];
    __shared__ float s_sc[32];
    __shared__ float s_att[32];
    __shared__ int   s_eid[32];
    __shared__ int   s_rid[32];

    int b   = blockIdx.x;
    int tid = threadIdx.x;

    int ib = idx[b];
    ib = min(max(ib, 0), N_ENTS - 1);

    if (tid < 32) {
        int e = adj_ent[(size_t)ib * KNBR + tid];
        s_eid[tid] = min(max(e, 0), N_ENTS - 1);
        int r = adj_rel[(size_t)ib * KNBR + tid];
        s_rid[tid] = min(max(r, 0), N_RELS - 1);
    }
    s_hr[tid] = g_TrT[(size_t)ib * EDIM + tid];
    s_h[tid]  = g_EntN[(size_t)ib * EDIM + tid];
    __syncthreads();

    int w = tid >> 5, l = tid & 31;
    float4 hr4 = *(const float4*)(s_hr + l * 4);

    #pragma unroll
    for (int kk = 0; kk < 8; kk++) {
        int k = w * 8 + kk;
        int e = s_eid[k], r = s_rid[k];
        float4 tr = *(const float4*)(g_TrT + (size_t)e * EDIM + l * 4);
        float4 rv = *(const float4*)(g_RelN + (size_t)r * EDIM + l * 4);
        float p = tanhf(hr4.x + rv.x) * tr.x + tanhf(hr4.y + rv.y) * tr.y +
                  tanhf(hr4.z + rv.z) * tr.z + tanhf(hr4.w + rv.w) * tr.w;
        #pragma unroll
        for (int o = 16; o; o >>= 1) p += __shfl_xor_sync(0xffffffffu, p, o);
        if (l == 0) s_sc[k] = p;
    }
    __syncthreads();

    if (tid < 32) {
        float sc = s_sc[tid];
        float mx = sc;
        #pragma unroll
        for (int o = 16; o; o >>= 1) mx = fmaxf(mx, __shfl_xor_sync(0xffffffffu, mx, o));
        float ex = __expf(sc - mx);
        float sum = ex;
        #pragma unroll
        for (int o = 16; o; o >>= 1) sum += __shfl_xor_sync(0xffffffffu, sum, o);
        s_att[tid] = ex / sum;
    }
    __syncthreads();

    float acc = 0.f;
    #pragma unroll
    for (int k = 0; k < KNBR; k++)
        acc = fmaf(s_att[k], g_EntN[(size_t)s_eid[k] * EDIM + tid], acc);

    float hv = s_h[tid];
    float x1 = hv + acc, x2 = hv * acc;
    size_t o = (size_t)b * EDIM + tid;
    __nv_bfloat16 h1 = __float2bfloat16(x1);
    g_X1h[o] = h1;
    g_X1l[o] = __float2bfloat16(x1 - __bfloat162float(h1));
    __nv_bfloat16 h2 = __float2bfloat16(x2);
    g_X2h[o] = h2;
    g_X2l[o] = __float2bfloat16(x2 - __bfloat162float(h2));
}

// ---------------- launch --------------------------------------------------------------
extern "C" void kernel_launch(void* const* d_in, const int* in_sizes, int n_in,
                              void* d_out, int out_size) {
    const int*   idx     = (const int*)d_in[0];
    const int*   adj_ent = (const int*)d_in[1];
    const int*   adj_rel = (const int*)d_in[2];
    const float* ent     = (const float*)d_in[3];
    const float* rel     = (const float*)d_in[4];
    const float* Wr_w    = (const float*)d_in[5];
    const float* Wr_b    = (const float*)d_in[6];
    const float* W1_w    = (const float*)d_in[7];
    const float* W1_b    = (const float*)d_in[8];
    const float* W2_w    = (const float*)d_in[9];
    const float* W2_b    = (const float*)d_in[10];
    float* out = (float*)d_out;

    cudaFuncSetAttribute(k_gemm2<0>, cudaFuncAttributeMaxDynamicSharedMemorySize, SMEM_MM);
    cudaFuncSetAttribute(k_gemm2<1>, cudaFuncAttributeMaxDynamicSharedMemorySize, SMEM_MM);
    cudaFuncSetAttribute(k_gemm2<2>, cudaFuncAttributeMaxDynamicSharedMemorySize, SMEM_MM);

    __nv_bfloat16 *EntH, *EntL, *WsH, *WsL, *X1h, *X1l, *X2h, *X2l;
    float *TrT;
    cudaGetSymbolAddress((void**)&EntH, g_EntH);
    cudaGetSymbolAddress((void**)&EntL, g_EntL);
    cudaGetSymbolAddress((void**)&WsH,  g_WsH);
    cudaGetSymbolAddress((void**)&WsL,  g_WsL);
    cudaGetSymbolAddress((void**)&X1h,  g_X1h);
    cudaGetSymbolAddress((void**)&X1l,  g_X1l);
    cudaGetSymbolAddress((void**)&X2h,  g_X2h);
    cudaGetSymbolAddress((void**)&X2l,  g_X2l);
    cudaGetSymbolAddress((void**)&TrT,  g_TrT);

    dim3 gw(EDIM * EDIM / 256, 3);
    k_split_w<<<gw, 256>>>(Wr_w, W1_w, W2_w);
    k_normalize<<<(N_ENTS + N_RELS + 7) / 8, 256>>>(ent, rel);
    k_gemm2<0><<<(N_ENTS + 63) / 64, 256, SMEM_MM>>>(EntH, EntL, WsH, WsL, Wr_b, TrT, N_ENTS);
    k_main<<<BATCH, 128>>>(idx, adj_ent, adj_rel);
    k_gemm2<1><<<BATCH / 64, 256, SMEM_MM>>>(X1h, X1l, WsH + EDIM * EDIM,
                                             WsL + EDIM * EDIM, W1_b, out, BATCH);
    k_gemm2<2><<<BATCH / 64, 256, SMEM_MM>>>(X2h, X2l, WsH + 2 * EDIM * EDIM,
                                             WsL + 2 * EDIM * EDIM, W2_b, out, BATCH);
}

// round 6
// speedup vs baseline: 1.2619x; 1.2619x over previous
#include <cuda_runtime.h>
#include <cuda_bf16.h>
#include <math.h>
#include <stdint.h>

#define N_ENTS  100000
#define N_RELS  64
#define EDIM    128
#define KNBR    32
#define BATCH   16384

// ---------------- device-global scratch ------------------------------------------
__device__ float         g_EntN[(size_t)N_ENTS * EDIM];   // maxnorm(ent) fp32
__device__ __nv_bfloat16 g_TrTb[(size_t)N_ENTS * EDIM];   // (EntN @ Wr^T + b) bf16
__device__ float         g_RelN[(size_t)N_RELS * EDIM];
__device__ float         g_X1  [(size_t)BATCH * EDIM];
__device__ float         g_X2  [(size_t)BATCH * EDIM];

// ---------------- helpers ----------------------------------------------------------
__device__ __forceinline__ uint32_t smem_u32(const void* p) {
    uint32_t a;
    asm("{ .reg .u64 t; cvta.to.shared.u64 t, %1; cvt.u32.u64 %0, t; }" : "=r"(a) : "l"(p));
    return a;
}
__device__ __forceinline__ void ldmx4(uint32_t& r0, uint32_t& r1, uint32_t& r2, uint32_t& r3,
                                      uint32_t addr) {
    asm volatile("ldmatrix.sync.aligned.m8n8.x4.shared.b16 {%0,%1,%2,%3}, [%4];"
                 : "=r"(r0), "=r"(r1), "=r"(r2), "=r"(r3) : "r"(addr));
}
__device__ __forceinline__ void mma_bf16(float* d, const uint32_t* a, const uint32_t* b) {
    asm volatile(
        "mma.sync.aligned.m16n8k16.row.col.f32.bf16.bf16.f32 "
        "{%0,%1,%2,%3}, {%4,%5,%6,%7}, {%8,%9}, {%0,%1,%2,%3};"
        : "+f"(d[0]), "+f"(d[1]), "+f"(d[2]), "+f"(d[3])
        : "r"(a[0]), "r"(a[1]), "r"(a[2]), "r"(a[3]), "r"(b[0]), "r"(b[1]));
}
__device__ __forceinline__ uint32_t pk_bf2(__nv_bfloat16 a, __nv_bfloat16 b) {
    __nv_bfloat162 t(a, b);
    return *(uint32_t*)&t;
}
// fast exact-saturating tanh: 1 - 2/(e^{2x}+1)
__device__ __forceinline__ float tanh_fast(float x) {
    float e = __expf(2.0f * x);
    return 1.0f - 2.0f / (e + 1.0f);
}

// padded bf16 tiles, row stride 136 elems (272 B) -> conflict-free ldmatrix
#define LDT 136
#define TILE_B (128 * LDT * 2)   // 34816
#define OFF_BIAS 0
// 3-pass kernel (gemm1/2): Ah, Al, Bh, Bl
#define OFF_AH   512
#define OFF_AL   (512 + TILE_B)
#define OFF_BH   (512 + 2 * TILE_B)
#define OFF_BL   (512 + 3 * TILE_B)
#define SMEM_MM  (512 + 4 * TILE_B)    // 139,776 B
// 2-pass kernel (gemm0): Ah, Al, Bh
#define SMEM_TRT (512 + 3 * TILE_B)    // 104,960 B

// split fp32 tile (rows >= rows_valid zeroed) into bf16 hi/lo in padded smem
__device__ __forceinline__ void load_split(const float* __restrict__ src, int rows_valid,
                                           char* sm, int off_h, int off_l, int tid) {
    #pragma unroll
    for (int i = 0; i < 8; i++) {
        int g = tid + i * 256;
        int row = g >> 4, c8 = g & 15, col0 = c8 * 8;
        float4 v0 = make_float4(0.f, 0.f, 0.f, 0.f), v1 = v0;
        if (row < rows_valid) {
            const float4* p = (const float4*)src + (size_t)row * 32 + c8 * 2;
            v0 = p[0];
            v1 = p[1];
        }
        float f[8] = {v0.x, v0.y, v0.z, v0.w, v1.x, v1.y, v1.z, v1.w};
        __nv_bfloat16 h[8], l[8];
        #pragma unroll
        for (int j = 0; j < 8; j++) {
            h[j] = __float2bfloat16(f[j]);
            l[j] = __float2bfloat16(f[j] - __bfloat162float(h[j]));
        }
        uint4 hv = make_uint4(pk_bf2(h[0], h[1]), pk_bf2(h[2], h[3]),
                              pk_bf2(h[4], h[5]), pk_bf2(h[6], h[7]));
        uint4 lv = make_uint4(pk_bf2(l[0], l[1]), pk_bf2(l[2], l[3]),
                              pk_bf2(l[4], l[5]), pk_bf2(l[6], l[7]));
        size_t o = (size_t)row * LDT * 2 + col0 * 2;
        *(uint4*)(sm + off_h + o) = hv;
        *(uint4*)(sm + off_l + o) = lv;
    }
}
// hi-only variant
__device__ __forceinline__ void load_hi(const float* __restrict__ src, int rows_valid,
                                        char* sm, int off_h, int tid) {
    #pragma unroll
    for (int i = 0; i < 8; i++) {
        int g = tid + i * 256;
        int row = g >> 4, c8 = g & 15, col0 = c8 * 8;
        float4 v0 = make_float4(0.f, 0.f, 0.f, 0.f), v1 = v0;
        if (row < rows_valid) {
            const float4* p = (const float4*)src + (size_t)row * 32 + c8 * 2;
            v0 = p[0];
            v1 = p[1];
        }
        float f[8] = {v0.x, v0.y, v0.z, v0.w, v1.x, v1.y, v1.z, v1.w};
        __nv_bfloat16 h[8];
        #pragma unroll
        for (int j = 0; j < 8; j++) h[j] = __float2bfloat16(f[j]);
        uint4 hv = make_uint4(pk_bf2(h[0], h[1]), pk_bf2(h[2], h[3]),
                              pk_bf2(h[4], h[5]), pk_bf2(h[6], h[7]));
        *(uint4*)(sm + off_h + (size_t)row * LDT * 2 + col0 * 2) = hv;
    }
}

// ---------------- gemm0: TrTb[M,128] = bf16(A[M,128] @ B^T + bias), 2-pass ----------
__global__ __launch_bounds__(256) void k_gemm_trt(const float* __restrict__ A,
                                                  const float* __restrict__ B,
                                                  const float* __restrict__ bias,
                                                  __nv_bfloat16* __restrict__ C, int M) {
    extern __shared__ char sm[];
    uint32_t smb = smem_u32(sm);
    int tid  = threadIdx.x;
    int wid  = tid >> 5, lane = tid & 31;
    int wy   = wid >> 2, wx = wid & 3;
    int m0   = blockIdx.x * 128;

    if (tid < 128) ((float*)(sm + OFF_BIAS))[tid] = bias[tid];
    load_split(A + (size_t)m0 * EDIM, M - m0, sm, OFF_AH, OFF_AL, tid);
    load_hi(B, 128, sm, OFF_BH, tid);
    __syncthreads();

    int rowA  = wy * 64 + (lane & 15);
    int colA  = (lane >> 4) * 8;
    int nrow  = wx * 32 + (lane & 7) + ((lane >> 4) ? 8 : 0);
    int kaddB = ((lane >> 3) & 1) * 8;

    uint32_t bB = smb + OFF_BH;

    float d[4][4][4];
    #pragma unroll
    for (int i = 0; i < 4; i++)
        #pragma unroll
        for (int j = 0; j < 4; j++)
            #pragma unroll
            for (int q = 0; q < 4; q++) d[i][j][q] = 0.f;

    #pragma unroll
    for (int pass = 0; pass < 2; pass++) {
        uint32_t aB = smb + ((pass == 1) ? OFF_AL : OFF_AH);
        #pragma unroll
        for (int ks = 0; ks < 8; ks++) {
            int k0 = ks * 16;
            uint32_t a[4][4];
            #pragma unroll
            for (int mi = 0; mi < 4; mi++) {
                uint32_t addr = aB + (uint32_t)(((rowA + mi * 16) * LDT + k0 + colA) * 2);
                ldmx4(a[mi][0], a[mi][1], a[mi][2], a[mi][3], addr);
            }
            uint32_t b[4][2];
            #pragma unroll
            for (int nj2 = 0; nj2 < 2; nj2++) {
                uint32_t addr = bB + (uint32_t)(((nrow + nj2 * 16) * LDT + k0 + kaddB) * 2);
                uint32_t r0, r1, r2, r3;
                ldmx4(r0, r1, r2, r3, addr);
                b[nj2 * 2 + 0][0] = r0; b[nj2 * 2 + 0][1] = r1;
                b[nj2 * 2 + 1][0] = r2; b[nj2 * 2 + 1][1] = r3;
            }
            #pragma unroll
            for (int mi = 0; mi < 4; mi++)
                #pragma unroll
                for (int nj = 0; nj < 4; nj++)
                    mma_bf16(d[mi][nj], a[mi], b[nj]);
        }
    }

    const float* sb = (const float*)(sm + OFF_BIAS);
    int qrow = lane >> 2, qcol = (lane & 3) * 2;
    #pragma unroll
    for (int mi = 0; mi < 4; mi++) {
        #pragma unroll
        for (int half = 0; half < 2; half++) {
            int gm = m0 + wy * 64 + mi * 16 + qrow + half * 8;
            if (gm < M) {
                #pragma unroll
                for (int nj = 0; nj < 4; nj++) {
                    int gc = wx * 32 + nj * 8 + qcol;
                    float x0 = d[mi][nj][half * 2 + 0] + sb[gc];
                    float x1 = d[mi][nj][half * 2 + 1] + sb[gc + 1];
                    *(uint32_t*)(C + (size_t)gm * 128 + gc) =
                        pk_bf2(__float2bfloat16(x0), __float2bfloat16(x1));
                }
            }
        }
    }
}

// ---------------- gemm1/2: C = epi(A @ B^T + bias), 3-pass (round-3 proven) ---------
// MODE 1: store leaky; MODE 2: += leaky
template <int MODE>
__global__ __launch_bounds__(256, 1) void k_gemm_mma(const float* __restrict__ A,
                                                     const float* __restrict__ B,
                                                     const float* __restrict__ bias,
                                                     float* __restrict__ C, int M) {
    extern __shared__ char sm[];
    uint32_t smb = smem_u32(sm);
    int tid  = threadIdx.x;
    int wid  = tid >> 5, lane = tid & 31;
    int wy   = wid >> 2, wx = wid & 3;
    int m0   = blockIdx.x * 128;

    if (tid < 128) ((float*)(sm + OFF_BIAS))[tid] = bias[tid];
    load_split(A + (size_t)m0 * EDIM, M - m0, sm, OFF_AH, OFF_AL, tid);
    load_split(B, 128, sm, OFF_BH, OFF_BL, tid);
    __syncthreads();

    int rowA  = wy * 64 + (lane & 15);
    int colA  = (lane >> 4) * 8;
    int nrow  = wx * 32 + (lane & 7) + ((lane >> 4) ? 8 : 0);
    int kaddB = ((lane >> 3) & 1) * 8;

    uint32_t aBaseH = smb + OFF_AH, aBaseL = smb + OFF_AL;
    uint32_t bBaseH = smb + OFF_BH, bBaseL = smb + OFF_BL;

    float d[4][4][4];
    #pragma unroll
    for (int i = 0; i < 4; i++)
        #pragma unroll
        for (int j = 0; j < 4; j++)
            #pragma unroll
            for (int q = 0; q < 4; q++) d[i][j][q] = 0.f;

    #pragma unroll
    for (int ks = 0; ks < 8; ks++) {
        int k0 = ks * 16;
        #pragma unroll
        for (int pass = 0; pass < 3; pass++) {
            uint32_t aB = (pass == 2) ? aBaseL : aBaseH;
            uint32_t bB = (pass == 1) ? bBaseL : bBaseH;

            uint32_t a[4][4];
            #pragma unroll
            for (int mi = 0; mi < 4; mi++) {
                uint32_t addr = aB + (uint32_t)(((rowA + mi * 16) * LDT + k0 + colA) * 2);
                ldmx4(a[mi][0], a[mi][1], a[mi][2], a[mi][3], addr);
            }
            uint32_t b[4][2];
            #pragma unroll
            for (int nj2 = 0; nj2 < 2; nj2++) {
                uint32_t addr = bB + (uint32_t)(((nrow + nj2 * 16) * LDT + k0 + kaddB) * 2);
                uint32_t r0, r1, r2, r3;
                ldmx4(r0, r1, r2, r3, addr);
                b[nj2 * 2 + 0][0] = r0; b[nj2 * 2 + 0][1] = r1;
                b[nj2 * 2 + 1][0] = r2; b[nj2 * 2 + 1][1] = r3;
            }
            #pragma unroll
            for (int mi = 0; mi < 4; mi++)
                #pragma unroll
                for (int nj = 0; nj < 4; nj++)
                    mma_bf16(d[mi][nj], a[mi], b[nj]);
        }
    }

    const float* sb = (const float*)(sm + OFF_BIAS);
    int qrow = lane >> 2, qcol = (lane & 3) * 2;
    #pragma unroll
    for (int mi = 0; mi < 4; mi++) {
        #pragma unroll
        for (int half = 0; half < 2; half++) {
            int gm = m0 + wy * 64 + mi * 16 + qrow + half * 8;
            if (gm < M) {
                #pragma unroll
                for (int nj = 0; nj < 4; nj++) {
                    int gc = wx * 32 + nj * 8 + qcol;
                    float x0 = d[mi][nj][half * 2 + 0] + sb[gc];
                    float x1 = d[mi][nj][half * 2 + 1] + sb[gc + 1];
                    x0 = (x0 > 0.f) ? x0 : 0.2f * x0;
                    x1 = (x1 > 0.f) ? x1 : 0.2f * x1;
                    float2* p = (float2*)(C + (size_t)gm * 128 + gc);
                    if (MODE == 2) {
                        float2 c = *p;
                        x0 += c.x;
                        x1 += c.y;
                    }
                    *p = make_float2(x0, x1);
                }
            }
        }
    }
}

// ---------------- K1: row max-norm --------------------------------------------------
__global__ __launch_bounds__(256) void k_normalize(const float* __restrict__ ent,
                                                   const float* __restrict__ rel) {
    int row = blockIdx.x * 8 + (threadIdx.x >> 5);
    int l   = threadIdx.x & 31;
    const float* src;
    float* dst;
    if (row < N_ENTS) {
        src = ent + (size_t)row * EDIM;
        dst = g_EntN + (size_t)row * EDIM;
    } else {
        int r = row - N_ENTS;
        if (r >= N_RELS) return;
        src = rel + (size_t)r * EDIM;
        dst = g_RelN + (size_t)r * EDIM;
    }
    float4 v = ((const float4*)src)[l];
    float ss = v.x * v.x + v.y * v.y + v.z * v.z + v.w * v.w;
    #pragma unroll
    for (int o = 16; o; o >>= 1) ss += __shfl_xor_sync(0xffffffffu, ss, o);
    float n = sqrtf(ss);
    float s = fminf(1.0f, 1.0f / fmaxf(n, 1e-12f));
    ((float4*)dst)[l] = make_float4(v.x * s, v.y * s, v.z * s, v.w * s);
}

// ---------------- K3: attention + aggregation ----------------------------------------
__global__ __launch_bounds__(128) void k_main(const int* __restrict__ idx,
                                              const int* __restrict__ adj_ent,
                                              const int* __restrict__ adj_rel) {
    __shared__ __align__(16) float s_hr[128];
    __shared__ __align__(16) float s_h[128];
    __shared__ float s_sc[32];
    __shared__ float s_att[32];
    __shared__ int   s_eid[32];
    __shared__ int   s_rid[32];

    int b   = blockIdx.x;
    int tid = threadIdx.x;

    int ib = idx[b];
    ib = min(max(ib, 0), N_ENTS - 1);

    if (tid < 32) {
        int e = adj_ent[(size_t)ib * KNBR + tid];
        s_eid[tid] = min(max(e, 0), N_ENTS - 1);
        int r = adj_rel[(size_t)ib * KNBR + tid];
        s_rid[tid] = min(max(r, 0), N_RELS - 1);
    }
    s_hr[tid] = __bfloat162float(g_TrTb[(size_t)ib * EDIM + tid]);
    s_h[tid]  = g_EntN[(size_t)ib * EDIM + tid];
    __syncthreads();

    int w = tid >> 5, l = tid & 31;
    float4 hr4 = *(const float4*)(s_hr + l * 4);

    // scores: warp w owns k = w*8..w*8+7; lane covers 4 dims; tr gathered in bf16
    #pragma unroll
    for (int kk = 0; kk < 8; kk++) {
        int k = w * 8 + kk;
        int e = s_eid[k], r = s_rid[k];
        uint2 trb = *(const uint2*)(g_TrTb + (size_t)e * EDIM + l * 4);
        float2 t01 = __bfloat1622float2(*(const __nv_bfloat162*)&trb.x);
        float2 t23 = __bfloat1622float2(*(const __nv_bfloat162*)&trb.y);
        float4 rv = *(const float4*)(g_RelN + (size_t)r * EDIM + l * 4);
        float p = tanh_fast(hr4.x + rv.x) * t01.x + tanh_fast(hr4.y + rv.y) * t01.y +
                  tanh_fast(hr4.z + rv.z) * t23.x + tanh_fast(hr4.w + rv.w) * t23.y;
        #pragma unroll
        for (int o = 16; o; o >>= 1) p += __shfl_xor_sync(0xffffffffu, p, o);
        if (l == 0) s_sc[k] = p;
    }
    __syncthreads();

    if (tid < 32) {
        float sc = s_sc[tid];
        float mx = sc;
        #pragma unroll
        for (int o = 16; o; o >>= 1) mx = fmaxf(mx, __shfl_xor_sync(0xffffffffu, mx, o));
        float ex = __expf(sc - mx);
        float sum = ex;
        #pragma unroll
        for (int o = 16; o; o >>= 1) sum += __shfl_xor_sync(0xffffffffu, sum, o);
        s_att[tid] = ex / sum;
    }
    __syncthreads();

    float acc = 0.f;
    #pragma unroll
    for (int k = 0; k < KNBR; k++)
        acc = fmaf(s_att[k], g_EntN[(size_t)s_eid[k] * EDIM + tid], acc);

    float hv = s_h[tid];
    g_X1[(size_t)b * EDIM + tid] = hv + acc;
    g_X2[(size_t)b * EDIM + tid] = hv * acc;
}

// ---------------- launch ---------------------------------------------------------------
extern "C" void kernel_launch(void* const* d_in, const int* in_sizes, int n_in,
                              void* d_out, int out_size) {
    const int*   idx     = (const int*)d_in[0];
    const int*   adj_ent = (const int*)d_in[1];
    const int*   adj_rel = (const int*)d_in[2];
    const float* ent     = (const float*)d_in[3];
    const float* rel     = (const float*)d_in[4];
    const float* Wr_w    = (const float*)d_in[5];
    const float* Wr_b    = (const float*)d_in[6];
    const float* W1_w    = (const float*)d_in[7];
    const float* W1_b    = (const float*)d_in[8];
    const float* W2_w    = (const float*)d_in[9];
    const float* W2_b    = (const float*)d_in[10];
    float* out = (float*)d_out;

    cudaFuncSetAttribute(k_gemm_trt, cudaFuncAttributeMaxDynamicSharedMemorySize, SMEM_TRT);
    cudaFuncSetAttribute(k_gemm_mma<1>, cudaFuncAttributeMaxDynamicSharedMemorySize, SMEM_MM);
    cudaFuncSetAttribute(k_gemm_mma<2>, cudaFuncAttributeMaxDynamicSharedMemorySize, SMEM_MM);

    float *EntN, *X1, *X2;
    __nv_bfloat16* TrTb;
    cudaGetSymbolAddress((void**)&EntN, g_EntN);
    cudaGetSymbolAddress((void**)&TrTb, g_TrTb);
    cudaGetSymbolAddress((void**)&X1,   g_X1);
    cudaGetSymbolAddress((void**)&X2,   g_X2);

    k_normalize<<<(N_ENTS + N_RELS + 7) / 8, 256>>>(ent, rel);
    k_gemm_trt<<<(N_ENTS + 127) / 128, 256, SMEM_TRT>>>(EntN, Wr_w, Wr_b, TrTb, N_ENTS);
    k_main<<<BATCH, 128>>>(idx, adj_ent, adj_rel);
    k_gemm_mma<1><<<BATCH / 128, 256, SMEM_MM>>>(X1, W1_w, W1_b, out, BATCH);
    k_gemm_mma<2><<<BATCH / 128, 256, SMEM_MM>>>(X2, W2_w, W2_b, out, BATCH);
}

// round 7
// speedup vs baseline: 1.3323x; 1.0557x over previous
#include <cuda_runtime.h>
#include <cuda_bf16.h>
#include <math.h>
#include <stdint.h>

#define N_ENTS  100000
#define N_RELS  64
#define EDIM    128
#define KNBR    32
#define BATCH   16384

// ---------------- device-global scratch ------------------------------------------
__device__ float         g_EntN[(size_t)N_ENTS * EDIM];   // maxnorm(ent) fp32
__device__ __nv_bfloat16 g_TrTb[(size_t)N_ENTS * EDIM];   // (EntN @ Wr^T + b) bf16
__device__ float         g_RelN[(size_t)N_RELS * EDIM];
__device__ float         g_X1  [(size_t)BATCH * EDIM];
__device__ float         g_X2  [(size_t)BATCH * EDIM];

// ---------------- helpers ----------------------------------------------------------
__device__ __forceinline__ uint32_t smem_u32(const void* p) {
    uint32_t a;
    asm("{ .reg .u64 t; cvta.to.shared.u64 t, %1; cvt.u32.u64 %0, t; }" : "=r"(a) : "l"(p));
    return a;
}
__device__ __forceinline__ void ldmx4(uint32_t& r0, uint32_t& r1, uint32_t& r2, uint32_t& r3,
                                      uint32_t addr) {
    asm volatile("ldmatrix.sync.aligned.m8n8.x4.shared.b16 {%0,%1,%2,%3}, [%4];"
                 : "=r"(r0), "=r"(r1), "=r"(r2), "=r"(r3) : "r"(addr));
}
__device__ __forceinline__ void mma_bf16(float* d, const uint32_t* a, const uint32_t* b) {
    asm volatile(
        "mma.sync.aligned.m16n8k16.row.col.f32.bf16.bf16.f32 "
        "{%0,%1,%2,%3}, {%4,%5,%6,%7}, {%8,%9}, {%0,%1,%2,%3};"
        : "+f"(d[0]), "+f"(d[1]), "+f"(d[2]), "+f"(d[3])
        : "r"(a[0]), "r"(a[1]), "r"(a[2]), "r"(a[3]), "r"(b[0]), "r"(b[1]));
}
__device__ __forceinline__ uint32_t pk_bf2(__nv_bfloat16 a, __nv_bfloat16 b) {
    __nv_bfloat162 t(a, b);
    return *(uint32_t*)&t;
}
// fast exact-saturating tanh: 1 - 2/(e^{2x}+1)
__device__ __forceinline__ float tanh_fast(float x) {
    float e = __expf(2.0f * x);
    return 1.0f - 2.0f / (e + 1.0f);
}

// padded bf16 tiles, row stride 136 elems (272 B) -> conflict-free ldmatrix
#define LDT 136
#define TILE_B (128 * LDT * 2)   // 34816
#define OFF_BIAS 0
#define OFF_AH   512
#define OFF_AL   (512 + TILE_B)
#define OFF_BH   (512 + 2 * TILE_B)
#define OFF_BL   (512 + 3 * TILE_B)
#define SMEM_MM  (512 + 4 * TILE_B)    // 139,776 B (gemm1/2, 3-pass)
// fused TrT kernel: Ah + Bh only
#define OFF_BH1  (512 + TILE_B)
#define SMEM_TRT (512 + 2 * TILE_B)    // 70,144 B -> 2 CTAs/SM

// split fp32 tile into bf16 hi/lo in padded smem
__device__ __forceinline__ void load_split(const float* __restrict__ src, int rows_valid,
                                           char* sm, int off_h, int off_l, int tid) {
    #pragma unroll
    for (int i = 0; i < 8; i++) {
        int g = tid + i * 256;
        int row = g >> 4, c8 = g & 15, col0 = c8 * 8;
        float4 v0 = make_float4(0.f, 0.f, 0.f, 0.f), v1 = v0;
        if (row < rows_valid) {
            const float4* p = (const float4*)src + (size_t)row * 32 + c8 * 2;
            v0 = p[0];
            v1 = p[1];
        }
        float f[8] = {v0.x, v0.y, v0.z, v0.w, v1.x, v1.y, v1.z, v1.w};
        __nv_bfloat16 h[8], l[8];
        #pragma unroll
        for (int j = 0; j < 8; j++) {
            h[j] = __float2bfloat16(f[j]);
            l[j] = __float2bfloat16(f[j] - __bfloat162float(h[j]));
        }
        uint4 hv = make_uint4(pk_bf2(h[0], h[1]), pk_bf2(h[2], h[3]),
                              pk_bf2(h[4], h[5]), pk_bf2(h[6], h[7]));
        uint4 lv = make_uint4(pk_bf2(l[0], l[1]), pk_bf2(l[2], l[3]),
                              pk_bf2(l[4], l[5]), pk_bf2(l[6], l[7]));
        size_t o = (size_t)row * LDT * 2 + col0 * 2;
        *(uint4*)(sm + off_h + o) = hv;
        *(uint4*)(sm + off_l + o) = lv;
    }
}
// hi-only variant
__device__ __forceinline__ void load_hi(const float* __restrict__ src, int rows_valid,
                                        char* sm, int off_h, int tid) {
    #pragma unroll
    for (int i = 0; i < 8; i++) {
        int g = tid + i * 256;
        int row = g >> 4, c8 = g & 15, col0 = c8 * 8;
        float4 v0 = make_float4(0.f, 0.f, 0.f, 0.f), v1 = v0;
        if (row < rows_valid) {
            const float4* p = (const float4*)src + (size_t)row * 32 + c8 * 2;
            v0 = p[0];
            v1 = p[1];
        }
        float f[8] = {v0.x, v0.y, v0.z, v0.w, v1.x, v1.y, v1.z, v1.w};
        __nv_bfloat16 h[8];
        #pragma unroll
        for (int j = 0; j < 8; j++) h[j] = __float2bfloat16(f[j]);
        uint4 hv = make_uint4(pk_bf2(h[0], h[1]), pk_bf2(h[2], h[3]),
                              pk_bf2(h[4], h[5]), pk_bf2(h[6], h[7]));
        *(uint4*)(sm + off_h + (size_t)row * LDT * 2 + col0 * 2) = hv;
    }
}

// ---------- fused: per-row max-norm of ent tile -> EntN (fp32 gmem) + Ah (smem),
// then single-pass bf16 GEMM -> TrTb = bf16(EntN @ Wr^T + Wr_b) -----------------------
__global__ __launch_bounds__(256, 2) void k_trt_fused(const float* __restrict__ ent,
                                                      const float* __restrict__ Wr,
                                                      const float* __restrict__ bias,
                                                      __nv_bfloat16* __restrict__ C,
                                                      int M) {
    extern __shared__ char sm[];
    uint32_t smb = smem_u32(sm);
    int tid  = threadIdx.x;
    int wid  = tid >> 5, lane = tid & 31;
    int wy   = wid >> 2, wx = wid & 3;
    int m0   = blockIdx.x * 128;
    int rows_valid = M - m0;

    if (tid < 128) ((float*)(sm + OFF_BIAS))[tid] = bias[tid];

    // A prologue: load raw ent rows, row-maxnorm (16-lane shfl), emit EntN + smem bf16-hi
    #pragma unroll
    for (int i = 0; i < 8; i++) {
        int g = tid + i * 256;
        int row = g >> 4, c8 = g & 15, col0 = c8 * 8;
        float4 v0 = make_float4(0.f, 0.f, 0.f, 0.f), v1 = v0;
        if (row < rows_valid) {
            const float4* p = (const float4*)(ent + (size_t)(m0 + row) * EDIM) + c8 * 2;
            v0 = p[0];
            v1 = p[1];
        }
        float ss = v0.x * v0.x + v0.y * v0.y + v0.z * v0.z + v0.w * v0.w +
                   v1.x * v1.x + v1.y * v1.y + v1.z * v1.z + v1.w * v1.w;
        #pragma unroll
        for (int o = 8; o; o >>= 1) ss += __shfl_xor_sync(0xffffffffu, ss, o);
        float n = sqrtf(ss);
        float s = fminf(1.0f, 1.0f / fmaxf(n, 1e-12f));
        float f[8] = {v0.x * s, v0.y * s, v0.z * s, v0.w * s,
                      v1.x * s, v1.y * s, v1.z * s, v1.w * s};
        if (row < rows_valid) {
            float4* q = (float4*)(g_EntN + (size_t)(m0 + row) * EDIM) + c8 * 2;
            q[0] = make_float4(f[0], f[1], f[2], f[3]);
            q[1] = make_float4(f[4], f[5], f[6], f[7]);
        }
        __nv_bfloat16 h[8];
        #pragma unroll
        for (int j = 0; j < 8; j++) h[j] = __float2bfloat16(f[j]);
        uint4 hv = make_uint4(pk_bf2(h[0], h[1]), pk_bf2(h[2], h[3]),
                              pk_bf2(h[4], h[5]), pk_bf2(h[6], h[7]));
        *(uint4*)(sm + OFF_AH + (size_t)row * LDT * 2 + col0 * 2) = hv;
    }

    load_hi(Wr, 128, sm, OFF_BH1, tid);
    __syncthreads();

    int rowA  = wy * 64 + (lane & 15);
    int colA  = (lane >> 4) * 8;
    int nrow  = wx * 32 + (lane & 7) + ((lane >> 4) ? 8 : 0);
    int kaddB = ((lane >> 3) & 1) * 8;

    uint32_t aB = smb + OFF_AH, bB = smb + OFF_BH1;

    float d[4][4][4];
    #pragma unroll
    for (int i = 0; i < 4; i++)
        #pragma unroll
        for (int j = 0; j < 4; j++)
            #pragma unroll
            for (int q = 0; q < 4; q++) d[i][j][q] = 0.f;

    #pragma unroll
    for (int ks = 0; ks < 8; ks++) {
        int k0 = ks * 16;
        uint32_t a[4][4];
        #pragma unroll
        for (int mi = 0; mi < 4; mi++) {
            uint32_t addr = aB + (uint32_t)(((rowA + mi * 16) * LDT + k0 + colA) * 2);
            ldmx4(a[mi][0], a[mi][1], a[mi][2], a[mi][3], addr);
        }
        uint32_t b[4][2];
        #pragma unroll
        for (int nj2 = 0; nj2 < 2; nj2++) {
            uint32_t addr = bB + (uint32_t)(((nrow + nj2 * 16) * LDT + k0 + kaddB) * 2);
            uint32_t r0, r1, r2, r3;
            ldmx4(r0, r1, r2, r3, addr);
            b[nj2 * 2 + 0][0] = r0; b[nj2 * 2 + 0][1] = r1;
            b[nj2 * 2 + 1][0] = r2; b[nj2 * 2 + 1][1] = r3;
        }
        #pragma unroll
        for (int mi = 0; mi < 4; mi++)
            #pragma unroll
            for (int nj = 0; nj < 4; nj++)
                mma_bf16(d[mi][nj], a[mi], b[nj]);
    }

    const float* sb = (const float*)(sm + OFF_BIAS);
    int qrow = lane >> 2, qcol = (lane & 3) * 2;
    #pragma unroll
    for (int mi = 0; mi < 4; mi++) {
        #pragma unroll
        for (int half = 0; half < 2; half++) {
            int gm = m0 + wy * 64 + mi * 16 + qrow + half * 8;
            if (gm < M) {
                #pragma unroll
                for (int nj = 0; nj < 4; nj++) {
                    int gc = wx * 32 + nj * 8 + qcol;
                    float x0 = d[mi][nj][half * 2 + 0] + sb[gc];
                    float x1 = d[mi][nj][half * 2 + 1] + sb[gc + 1];
                    *(uint32_t*)(C + (size_t)gm * 128 + gc) =
                        pk_bf2(__float2bfloat16(x0), __float2bfloat16(x1));
                }
            }
        }
    }
}

// ---------------- gemm1/2: C = epi(A @ B^T + bias), 3-pass ---------------------------
// MODE 1: store leaky; MODE 2: += leaky
template <int MODE>
__global__ __launch_bounds__(256, 1) void k_gemm_mma(const float* __restrict__ A,
                                                     const float* __restrict__ B,
                                                     const float* __restrict__ bias,
                                                     float* __restrict__ C, int M) {
    extern __shared__ char sm[];
    uint32_t smb = smem_u32(sm);
    int tid  = threadIdx.x;
    int wid  = tid >> 5, lane = tid & 31;
    int wy   = wid >> 2, wx = wid & 3;
    int m0   = blockIdx.x * 128;

    if (tid < 128) ((float*)(sm + OFF_BIAS))[tid] = bias[tid];
    load_split(A + (size_t)m0 * EDIM, M - m0, sm, OFF_AH, OFF_AL, tid);
    load_split(B, 128, sm, OFF_BH, OFF_BL, tid);
    __syncthreads();

    int rowA  = wy * 64 + (lane & 15);
    int colA  = (lane >> 4) * 8;
    int nrow  = wx * 32 + (lane & 7) + ((lane >> 4) ? 8 : 0);
    int kaddB = ((lane >> 3) & 1) * 8;

    uint32_t aBaseH = smb + OFF_AH, aBaseL = smb + OFF_AL;
    uint32_t bBaseH = smb + OFF_BH, bBaseL = smb + OFF_BL;

    float d[4][4][4];
    #pragma unroll
    for (int i = 0; i < 4; i++)
        #pragma unroll
        for (int j = 0; j < 4; j++)
            #pragma unroll
            for (int q = 0; q < 4; q++) d[i][j][q] = 0.f;

    #pragma unroll
    for (int ks = 0; ks < 8; ks++) {
        int k0 = ks * 16;
        #pragma unroll
        for (int pass = 0; pass < 3; pass++) {
            uint32_t aB = (pass == 2) ? aBaseL : aBaseH;
            uint32_t bB = (pass == 1) ? bBaseL : bBaseH;

            uint32_t a[4][4];
            #pragma unroll
            for (int mi = 0; mi < 4; mi++) {
                uint32_t addr = aB + (uint32_t)(((rowA + mi * 16) * LDT + k0 + colA) * 2);
                ldmx4(a[mi][0], a[mi][1], a[mi][2], a[mi][3], addr);
            }
            uint32_t b[4][2];
            #pragma unroll
            for (int nj2 = 0; nj2 < 2; nj2++) {
                uint32_t addr = bB + (uint32_t)(((nrow + nj2 * 16) * LDT + k0 + kaddB) * 2);
                uint32_t r0, r1, r2, r3;
                ldmx4(r0, r1, r2, r3, addr);
                b[nj2 * 2 + 0][0] = r0; b[nj2 * 2 + 0][1] = r1;
                b[nj2 * 2 + 1][0] = r2; b[nj2 * 2 + 1][1] = r3;
            }
            #pragma unroll
            for (int mi = 0; mi < 4; mi++)
                #pragma unroll
                for (int nj = 0; nj < 4; nj++)
                    mma_bf16(d[mi][nj], a[mi], b[nj]);
        }
    }

    const float* sb = (const float*)(sm + OFF_BIAS);
    int qrow = lane >> 2, qcol = (lane & 3) * 2;
    #pragma unroll
    for (int mi = 0; mi < 4; mi++) {
        #pragma unroll
        for (int half = 0; half < 2; half++) {
            int gm = m0 + wy * 64 + mi * 16 + qrow + half * 8;
            if (gm < M) {
                #pragma unroll
                for (int nj = 0; nj < 4; nj++) {
                    int gc = wx * 32 + nj * 8 + qcol;
                    float x0 = d[mi][nj][half * 2 + 0] + sb[gc];
                    float x1 = d[mi][nj][half * 2 + 1] + sb[gc + 1];
                    x0 = (x0 > 0.f) ? x0 : 0.2f * x0;
                    x1 = (x1 > 0.f) ? x1 : 0.2f * x1;
                    float2* p = (float2*)(C + (size_t)gm * 128 + gc);
                    if (MODE == 2) {
                        float2 c = *p;
                        x0 += c.x;
                        x1 += c.y;
                    }
                    *p = make_float2(x0, x1);
                }
            }
        }
    }
}

// ---------------- rel-table max-norm (64 rows) ---------------------------------------
__global__ __launch_bounds__(256) void k_norm_rel(const float* __restrict__ rel) {
    int row = blockIdx.x * 8 + (threadIdx.x >> 5);
    int l   = threadIdx.x & 31;
    if (row >= N_RELS) return;
    float4 v = ((const float4*)(rel + (size_t)row * EDIM))[l];
    float ss = v.x * v.x + v.y * v.y + v.z * v.z + v.w * v.w;
    #pragma unroll
    for (int o = 16; o; o >>= 1) ss += __shfl_xor_sync(0xffffffffu, ss, o);
    float n = sqrtf(ss);
    float s = fminf(1.0f, 1.0f / fmaxf(n, 1e-12f));
    ((float4*)(g_RelN + (size_t)row * EDIM))[l] = make_float4(v.x * s, v.y * s, v.z * s, v.w * s);
}

// ---------------- K3: attention + aggregation ----------------------------------------
__global__ __launch_bounds__(128) void k_main(const int* __restrict__ idx,
                                              const int* __restrict__ adj_ent,
                                              const int* __restrict__ adj_rel) {
    __shared__ __align__(16) float s_hr[128];
    __shared__ __align__(16) float s_h[128];
    __shared__ float s_sc[32];
    __shared__ float s_att[32];
    __shared__ int   s_eid[32];
    __shared__ int   s_rid[32];

    int b   = blockIdx.x;
    int tid = threadIdx.x;

    int ib = idx[b];
    ib = min(max(ib, 0), N_ENTS - 1);

    if (tid < 32) {
        int e = adj_ent[(size_t)ib * KNBR + tid];
        s_eid[tid] = min(max(e, 0), N_ENTS - 1);
        int r = adj_rel[(size_t)ib * KNBR + tid];
        s_rid[tid] = min(max(r, 0), N_RELS - 1);
    }
    s_hr[tid] = __bfloat162float(g_TrTb[(size_t)ib * EDIM + tid]);
    s_h[tid]  = g_EntN[(size_t)ib * EDIM + tid];
    __syncthreads();

    int w = tid >> 5, l = tid & 31;
    float4 hr4 = *(const float4*)(s_hr + l * 4);

    #pragma unroll
    for (int kk = 0; kk < 8; kk++) {
        int k = w * 8 + kk;
        int e = s_eid[k], r = s_rid[k];
        uint2 trb = *(const uint2*)(g_TrTb + (size_t)e * EDIM + l * 4);
        float2 t01 = __bfloat1622float2(*(const __nv_bfloat162*)&trb.x);
        float2 t23 = __bfloat1622float2(*(const __nv_bfloat162*)&trb.y);
        float4 rv = *(const float4*)(g_RelN + (size_t)r * EDIM + l * 4);
        float p = tanh_fast(hr4.x + rv.x) * t01.x + tanh_fast(hr4.y + rv.y) * t01.y +
                  tanh_fast(hr4.z + rv.z) * t23.x + tanh_fast(hr4.w + rv.w) * t23.y;
        #pragma unroll
        for (int o = 16; o; o >>= 1) p += __shfl_xor_sync(0xffffffffu, p, o);
        if (l == 0) s_sc[k] = p;
    }
    __syncthreads();

    if (tid < 32) {
        float sc = s_sc[tid];
        float mx = sc;
        #pragma unroll
        for (int o = 16; o; o >>= 1) mx = fmaxf(mx, __shfl_xor_sync(0xffffffffu, mx, o));
        float ex = __expf(sc - mx);
        float sum = ex;
        #pragma unroll
        for (int o = 16; o; o >>= 1) sum += __shfl_xor_sync(0xffffffffu, sum, o);
        s_att[tid] = ex / sum;
    }
    __syncthreads();

    float acc = 0.f;
    #pragma unroll
    for (int k = 0; k < KNBR; k++)
        acc = fmaf(s_att[k], g_EntN[(size_t)s_eid[k] * EDIM + tid], acc);

    float hv = s_h[tid];
    g_X1[(size_t)b * EDIM + tid] = hv + acc;
    g_X2[(size_t)b * EDIM + tid] = hv * acc;
}

// ---------------- launch ---------------------------------------------------------------
extern "C" void kernel_launch(void* const* d_in, const int* in_sizes, int n_in,
                              void* d_out, int out_size) {
    const int*   idx     = (const int*)d_in[0];
    const int*   adj_ent = (const int*)d_in[1];
    const int*   adj_rel = (const int*)d_in[2];
    const float* ent     = (const float*)d_in[3];
    const float* rel     = (const float*)d_in[4];
    const float* Wr_w    = (const float*)d_in[5];
    const float* Wr_b    = (const float*)d_in[6];
    const float* W1_w    = (const float*)d_in[7];
    const float* W1_b    = (const float*)d_in[8];
    const float* W2_w    = (const float*)d_in[9];
    const float* W2_b    = (const float*)d_in[10];
    float* out = (float*)d_out;

    cudaFuncSetAttribute(k_trt_fused, cudaFuncAttributeMaxDynamicSharedMemorySize, SMEM_TRT);
    cudaFuncSetAttribute(k_gemm_mma<1>, cudaFuncAttributeMaxDynamicSharedMemorySize, SMEM_MM);
    cudaFuncSetAttribute(k_gemm_mma<2>, cudaFuncAttributeMaxDynamicSharedMemorySize, SMEM_MM);

    float *X1, *X2;
    __nv_bfloat16* TrTb;
    cudaGetSymbolAddress((void**)&TrTb, g_TrTb);
    cudaGetSymbolAddress((void**)&X1,   g_X1);
    cudaGetSymbolAddress((void**)&X2,   g_X2);

    k_norm_rel<<<(N_RELS + 7) / 8, 256>>>(rel);
    k_trt_fused<<<(N_ENTS + 127) / 128, 256, SMEM_TRT>>>(ent, Wr_w, Wr_b, TrTb, N_ENTS);
    k_main<<<BATCH, 128>>>(idx, adj_ent, adj_rel);
    k_gemm_mma<1><<<BATCH / 128, 256, SMEM_MM>>>(X1, W1_w, W1_b, out, BATCH);
    k_gemm_mma<2><<<BATCH / 128, 256, SMEM_MM>>>(X2, W2_w, W2_b, out, BATCH);
}

// round 8
// speedup vs baseline: 1.4631x; 1.0982x over previous
#include <cuda_runtime.h>
#include <cuda_bf16.h>
#include <math.h>
#include <stdint.h>

#define N_ENTS  100000
#define N_RELS  64
#define EDIM    128
#define KNBR    32
#define BATCH   16384

// ---------------- device-global scratch ------------------------------------------
__device__ float         g_EntN[(size_t)N_ENTS * EDIM];   // maxnorm(ent) fp32
__device__ __nv_bfloat16 g_TrTb[(size_t)N_ENTS * EDIM];   // (EntN @ Wr^T + b) bf16
__device__ float         g_RelN[(size_t)N_RELS * EDIM];
__device__ float         g_X1  [(size_t)BATCH * EDIM];
__device__ float         g_X2  [(size_t)BATCH * EDIM];

// ---------------- helpers ----------------------------------------------------------
__device__ __forceinline__ uint32_t smem_u32(const void* p) {
    uint32_t a;
    asm("{ .reg .u64 t; cvta.to.shared.u64 t, %1; cvt.u32.u64 %0, t; }" : "=r"(a) : "l"(p));
    return a;
}
__device__ __forceinline__ void ldmx4(uint32_t& r0, uint32_t& r1, uint32_t& r2, uint32_t& r3,
                                      uint32_t addr) {
    asm volatile("ldmatrix.sync.aligned.m8n8.x4.shared.b16 {%0,%1,%2,%3}, [%4];"
                 : "=r"(r0), "=r"(r1), "=r"(r2), "=r"(r3) : "r"(addr));
}
__device__ __forceinline__ void mma_bf16(float* d, const uint32_t* a, const uint32_t* b) {
    asm volatile(
        "mma.sync.aligned.m16n8k16.row.col.f32.bf16.bf16.f32 "
        "{%0,%1,%2,%3}, {%4,%5,%6,%7}, {%8,%9}, {%0,%1,%2,%3};"
        : "+f"(d[0]), "+f"(d[1]), "+f"(d[2]), "+f"(d[3])
        : "r"(a[0]), "r"(a[1]), "r"(a[2]), "r"(a[3]), "r"(b[0]), "r"(b[1]));
}
__device__ __forceinline__ uint32_t pk_bf2(__nv_bfloat16 a, __nv_bfloat16 b) {
    __nv_bfloat162 t(a, b);
    return *(uint32_t*)&t;
}
// hardware tanh (MUFU.TANH, 1 op, sm_75+)
__device__ __forceinline__ float tanh_hw(float x) {
    float y;
    asm("tanh.approx.f32 %0, %1;" : "=f"(y) : "f"(x));
    return y;
}

// padded bf16 tiles, row stride 136 elems (272 B) -> conflict-free ldmatrix
#define LDT 136
#define TILE_B  (128 * LDT * 2)   // 34816
#define HTILE_B (64  * LDT * 2)   // 17408
#define OFF_BIAS 0
#define OFF_AH   512
#define OFF_AL   (512 + TILE_B)
// fused TrT kernel: Ah + Bh only
#define OFF_BH1  (512 + TILE_B)
#define SMEM_TRT (512 + 2 * TILE_B)               // 70,144 -> 2 CTAs/SM
// N-split gemm1/2: Ah, Al (full 128 rows) + Bh, Bl (64 rows)
#define OFF_BH2  (512 + 2 * TILE_B)
#define OFF_BL2  (512 + 2 * TILE_B + HTILE_B)
#define SMEM_N64 (512 + 2 * TILE_B + 2 * HTILE_B) // 104,960 -> 2 CTAs/SM

// split fp32 tile (128 rows) into bf16 hi/lo in padded smem
__device__ __forceinline__ void load_split(const float* __restrict__ src, int rows_valid,
                                           char* sm, int off_h, int off_l, int tid) {
    #pragma unroll
    for (int i = 0; i < 8; i++) {
        int g = tid + i * 256;
        int row = g >> 4, c8 = g & 15, col0 = c8 * 8;
        float4 v0 = make_float4(0.f, 0.f, 0.f, 0.f), v1 = v0;
        if (row < rows_valid) {
            const float4* p = (const float4*)src + (size_t)row * 32 + c8 * 2;
            v0 = p[0];
            v1 = p[1];
        }
        float f[8] = {v0.x, v0.y, v0.z, v0.w, v1.x, v1.y, v1.z, v1.w};
        __nv_bfloat16 h[8], l[8];
        #pragma unroll
        for (int j = 0; j < 8; j++) {
            h[j] = __float2bfloat16(f[j]);
            l[j] = __float2bfloat16(f[j] - __bfloat162float(h[j]));
        }
        uint4 hv = make_uint4(pk_bf2(h[0], h[1]), pk_bf2(h[2], h[3]),
                              pk_bf2(h[4], h[5]), pk_bf2(h[6], h[7]));
        uint4 lv = make_uint4(pk_bf2(l[0], l[1]), pk_bf2(l[2], l[3]),
                              pk_bf2(l[4], l[5]), pk_bf2(l[6], l[7]));
        size_t o = (size_t)row * LDT * 2 + col0 * 2;
        *(uint4*)(sm + off_h + o) = hv;
        *(uint4*)(sm + off_l + o) = lv;
    }
}
// 64-row variant
__device__ __forceinline__ void load_split64(const float* __restrict__ src,
                                             char* sm, int off_h, int off_l, int tid) {
    #pragma unroll
    for (int i = 0; i < 4; i++) {
        int g = tid + i * 256;
        int row = g >> 4, c8 = g & 15, col0 = c8 * 8;
        const float4* p = (const float4*)src + (size_t)row * 32 + c8 * 2;
        float4 v0 = p[0], v1 = p[1];
        float f[8] = {v0.x, v0.y, v0.z, v0.w, v1.x, v1.y, v1.z, v1.w};
        __nv_bfloat16 h[8], l[8];
        #pragma unroll
        for (int j = 0; j < 8; j++) {
            h[j] = __float2bfloat16(f[j]);
            l[j] = __float2bfloat16(f[j] - __bfloat162float(h[j]));
        }
        uint4 hv = make_uint4(pk_bf2(h[0], h[1]), pk_bf2(h[2], h[3]),
                              pk_bf2(h[4], h[5]), pk_bf2(h[6], h[7]));
        uint4 lv = make_uint4(pk_bf2(l[0], l[1]), pk_bf2(l[2], l[3]),
                              pk_bf2(l[4], l[5]), pk_bf2(l[6], l[7]));
        size_t o = (size_t)row * LDT * 2 + col0 * 2;
        *(uint4*)(sm + off_h + o) = hv;
        *(uint4*)(sm + off_l + o) = lv;
    }
}
// hi-only variant (128 rows)
__device__ __forceinline__ void load_hi(const float* __restrict__ src,
                                        char* sm, int off_h, int tid) {
    #pragma unroll
    for (int i = 0; i < 8; i++) {
        int g = tid + i * 256;
        int row = g >> 4, c8 = g & 15, col0 = c8 * 8;
        const float4* p = (const float4*)src + (size_t)row * 32 + c8 * 2;
        float4 v0 = p[0], v1 = p[1];
        float f[8] = {v0.x, v0.y, v0.z, v0.w, v1.x, v1.y, v1.z, v1.w};
        __nv_bfloat16 h[8];
        #pragma unroll
        for (int j = 0; j < 8; j++) h[j] = __float2bfloat16(f[j]);
        uint4 hv = make_uint4(pk_bf2(h[0], h[1]), pk_bf2(h[2], h[3]),
                              pk_bf2(h[4], h[5]), pk_bf2(h[6], h[7]));
        *(uint4*)(sm + off_h + (size_t)row * LDT * 2 + col0 * 2) = hv;
    }
}

// ---------- fused maxnorm + single-pass bf16 GEMM -> TrTb (proven round 7) ----------
__global__ __launch_bounds__(256, 2) void k_trt_fused(const float* __restrict__ ent,
                                                      const float* __restrict__ Wr,
                                                      const float* __restrict__ bias,
                                                      __nv_bfloat16* __restrict__ C,
                                                      int M) {
    extern __shared__ char sm[];
    uint32_t smb = smem_u32(sm);
    int tid  = threadIdx.x;
    int wid  = tid >> 5, lane = tid & 31;
    int wy   = wid >> 2, wx = wid & 3;
    int m0   = blockIdx.x * 128;
    int rows_valid = M - m0;

    if (tid < 128) ((float*)(sm + OFF_BIAS))[tid] = bias[tid];

    #pragma unroll
    for (int i = 0; i < 8; i++) {
        int g = tid + i * 256;
        int row = g >> 4, c8 = g & 15, col0 = c8 * 8;
        float4 v0 = make_float4(0.f, 0.f, 0.f, 0.f), v1 = v0;
        if (row < rows_valid) {
            const float4* p = (const float4*)(ent + (size_t)(m0 + row) * EDIM) + c8 * 2;
            v0 = p[0];
            v1 = p[1];
        }
        float ss = v0.x * v0.x + v0.y * v0.y + v0.z * v0.z + v0.w * v0.w +
                   v1.x * v1.x + v1.y * v1.y + v1.z * v1.z + v1.w * v1.w;
        #pragma unroll
        for (int o = 8; o; o >>= 1) ss += __shfl_xor_sync(0xffffffffu, ss, o);
        float n = sqrtf(ss);
        float s = fminf(1.0f, 1.0f / fmaxf(n, 1e-12f));
        float f[8] = {v0.x * s, v0.y * s, v0.z * s, v0.w * s,
                      v1.x * s, v1.y * s, v1.z * s, v1.w * s};
        if (row < rows_valid) {
            float4* q = (float4*)(g_EntN + (size_t)(m0 + row) * EDIM) + c8 * 2;
            q[0] = make_float4(f[0], f[1], f[2], f[3]);
            q[1] = make_float4(f[4], f[5], f[6], f[7]);
        }
        __nv_bfloat16 h[8];
        #pragma unroll
        for (int j = 0; j < 8; j++) h[j] = __float2bfloat16(f[j]);
        uint4 hv = make_uint4(pk_bf2(h[0], h[1]), pk_bf2(h[2], h[3]),
                              pk_bf2(h[4], h[5]), pk_bf2(h[6], h[7]));
        *(uint4*)(sm + OFF_AH + (size_t)row * LDT * 2 + col0 * 2) = hv;
    }

    load_hi(Wr, sm, OFF_BH1, tid);
    __syncthreads();

    int rowA  = wy * 64 + (lane & 15);
    int colA  = (lane >> 4) * 8;
    int nrow  = wx * 32 + (lane & 7) + ((lane >> 4) ? 8 : 0);
    int kaddB = ((lane >> 3) & 1) * 8;

    uint32_t aB = smb + OFF_AH, bB = smb + OFF_BH1;

    float d[4][4][4];
    #pragma unroll
    for (int i = 0; i < 4; i++)
        #pragma unroll
        for (int j = 0; j < 4; j++)
            #pragma unroll
            for (int q = 0; q < 4; q++) d[i][j][q] = 0.f;

    #pragma unroll
    for (int ks = 0; ks < 8; ks++) {
        int k0 = ks * 16;
        uint32_t a[4][4];
        #pragma unroll
        for (int mi = 0; mi < 4; mi++) {
            uint32_t addr = aB + (uint32_t)(((rowA + mi * 16) * LDT + k0 + colA) * 2);
            ldmx4(a[mi][0], a[mi][1], a[mi][2], a[mi][3], addr);
        }
        uint32_t b[4][2];
        #pragma unroll
        for (int nj2 = 0; nj2 < 2; nj2++) {
            uint32_t addr = bB + (uint32_t)(((nrow + nj2 * 16) * LDT + k0 + kaddB) * 2);
            uint32_t r0, r1, r2, r3;
            ldmx4(r0, r1, r2, r3, addr);
            b[nj2 * 2 + 0][0] = r0; b[nj2 * 2 + 0][1] = r1;
            b[nj2 * 2 + 1][0] = r2; b[nj2 * 2 + 1][1] = r3;
        }
        #pragma unroll
        for (int mi = 0; mi < 4; mi++)
            #pragma unroll
            for (int nj = 0; nj < 4; nj++)
                mma_bf16(d[mi][nj], a[mi], b[nj]);
    }

    const float* sb = (const float*)(sm + OFF_BIAS);
    int qrow = lane >> 2, qcol = (lane & 3) * 2;
    #pragma unroll
    for (int mi = 0; mi < 4; mi++) {
        #pragma unroll
        for (int half = 0; half < 2; half++) {
            int gm = m0 + wy * 64 + mi * 16 + qrow + half * 8;
            if (gm < M) {
                #pragma unroll
                for (int nj = 0; nj < 4; nj++) {
                    int gc = wx * 32 + nj * 8 + qcol;
                    float x0 = d[mi][nj][half * 2 + 0] + sb[gc];
                    float x1 = d[mi][nj][half * 2 + 1] + sb[gc + 1];
                    *(uint32_t*)(C + (size_t)gm * 128 + gc) =
                        pk_bf2(__float2bfloat16(x0), __float2bfloat16(x1));
                }
            }
        }
    }
}

// ------- gemm1/2, N-split: C[:, n0:n0+64] = epi(A @ B[n0:n0+64,:]^T + bias) ----------
// CTA tile 128(M) x 64(N), grid (M/128, 2), 2 CTAs/SM. 8 warps = 4(M) x 2(N), 32x32.
// 3-pass hi/lo. MODE 1: store leaky; MODE 2: += leaky
template <int MODE>
__global__ __launch_bounds__(256, 2) void k_gemm_n64(const float* __restrict__ A,
                                                     const float* __restrict__ B,
                                                     const float* __restrict__ bias,
                                                     float* __restrict__ C, int M) {
    extern __shared__ char sm[];
    uint32_t smb = smem_u32(sm);
    int tid  = threadIdx.x;
    int wid  = tid >> 5, lane = tid & 31;
    int wy   = wid >> 1, wx = wid & 1;          // 4 x 2 warp grid
    int m0   = blockIdx.x * 128;
    int n0   = blockIdx.y * 64;

    if (tid < 64) ((float*)(sm + OFF_BIAS))[tid] = bias[n0 + tid];
    load_split(A + (size_t)m0 * EDIM, M - m0, sm, OFF_AH, OFF_AL, tid);
    load_split64(B + (size_t)n0 * EDIM, sm, OFF_BH2, OFF_BL2, tid);
    __syncthreads();

    int rowA  = wy * 32 + (lane & 15);
    int colA  = (lane >> 4) * 8;
    int nrow  = wx * 32 + (lane & 7) + ((lane >> 4) ? 8 : 0);
    int kaddB = ((lane >> 3) & 1) * 8;

    uint32_t aBaseH = smb + OFF_AH, aBaseL = smb + OFF_AL;
    uint32_t bBaseH = smb + OFF_BH2, bBaseL = smb + OFF_BL2;

    float d[2][4][4];
    #pragma unroll
    for (int i = 0; i < 2; i++)
        #pragma unroll
        for (int j = 0; j < 4; j++)
            #pragma unroll
            for (int q = 0; q < 4; q++) d[i][j][q] = 0.f;

    #pragma unroll
    for (int ks = 0; ks < 8; ks++) {
        int k0 = ks * 16;
        #pragma unroll
        for (int pass = 0; pass < 3; pass++) {
            uint32_t aB = (pass == 2) ? aBaseL : aBaseH;
            uint32_t bB = (pass == 1) ? bBaseL : bBaseH;

            uint32_t a[2][4];
            #pragma unroll
            for (int mi = 0; mi < 2; mi++) {
                uint32_t addr = aB + (uint32_t)(((rowA + mi * 16) * LDT + k0 + colA) * 2);
                ldmx4(a[mi][0], a[mi][1], a[mi][2], a[mi][3], addr);
            }
            uint32_t b[4][2];
            #pragma unroll
            for (int nj2 = 0; nj2 < 2; nj2++) {
                uint32_t addr = bB + (uint32_t)(((nrow + nj2 * 16) * LDT + k0 + kaddB) * 2);
                uint32_t r0, r1, r2, r3;
                ldmx4(r0, r1, r2, r3, addr);
                b[nj2 * 2 + 0][0] = r0; b[nj2 * 2 + 0][1] = r1;
                b[nj2 * 2 + 1][0] = r2; b[nj2 * 2 + 1][1] = r3;
            }
            #pragma unroll
            for (int mi = 0; mi < 2; mi++)
                #pragma unroll
                for (int nj = 0; nj < 4; nj++)
                    mma_bf16(d[mi][nj], a[mi], b[nj]);
        }
    }

    const float* sb = (const float*)(sm + OFF_BIAS);
    int qrow = lane >> 2, qcol = (lane & 3) * 2;
    #pragma unroll
    for (int mi = 0; mi < 2; mi++) {
        #pragma unroll
        for (int half = 0; half < 2; half++) {
            int gm = m0 + wy * 32 + mi * 16 + qrow + half * 8;
            if (gm < M) {
                #pragma unroll
                for (int nj = 0; nj < 4; nj++) {
                    int gc = wx * 32 + nj * 8 + qcol;
                    float x0 = d[mi][nj][half * 2 + 0] + sb[gc];
                    float x1 = d[mi][nj][half * 2 + 1] + sb[gc + 1];
                    x0 = (x0 > 0.f) ? x0 : 0.2f * x0;
                    x1 = (x1 > 0.f) ? x1 : 0.2f * x1;
                    float2* p = (float2*)(C + (size_t)gm * 128 + n0 + gc);
                    if (MODE == 2) {
                        float2 c = *p;
                        x0 += c.x;
                        x1 += c.y;
                    }
                    *p = make_float2(x0, x1);
                }
            }
        }
    }
}

// ---------------- rel-table max-norm (64 rows) ---------------------------------------
__global__ __launch_bounds__(256) void k_norm_rel(const float* __restrict__ rel) {
    int row = blockIdx.x * 8 + (threadIdx.x >> 5);
    int l   = threadIdx.x & 31;
    if (row >= N_RELS) return;
    float4 v = ((const float4*)(rel + (size_t)row * EDIM))[l];
    float ss = v.x * v.x + v.y * v.y + v.z * v.z + v.w * v.w;
    #pragma unroll
    for (int o = 16; o; o >>= 1) ss += __shfl_xor_sync(0xffffffffu, ss, o);
    float n = sqrtf(ss);
    float s = fminf(1.0f, 1.0f / fmaxf(n, 1e-12f));
    ((float4*)(g_RelN + (size_t)row * EDIM))[l] = make_float4(v.x * s, v.y * s, v.z * s, v.w * s);
}

// ---------------- K3: attention + aggregation ----------------------------------------
__global__ __launch_bounds__(128) void k_main(const int* __restrict__ idx,
                                              const int* __restrict__ adj_ent,
                                              const int* __restrict__ adj_rel) {
    __shared__ __align__(16) float s_hr[128];
    __shared__ __align__(16) float s_h[128];
    __shared__ float s_sc[32];
    __shared__ float s_att[32];
    __shared__ int   s_eid[32];
    __shared__ int   s_rid[32];

    int b   = blockIdx.x;
    int tid = threadIdx.x;

    int ib = idx[b];
    ib = min(max(ib, 0), N_ENTS - 1);

    if (tid < 32) {
        int e = adj_ent[(size_t)ib * KNBR + tid];
        s_eid[tid] = min(max(e, 0), N_ENTS - 1);
        int r = adj_rel[(size_t)ib * KNBR + tid];
        s_rid[tid] = min(max(r, 0), N_RELS - 1);
    }
    s_hr[tid] = __bfloat162float(g_TrTb[(size_t)ib * EDIM + tid]);
    s_h[tid]  = g_EntN[(size_t)ib * EDIM + tid];
    __syncthreads();

    int w = tid >> 5, l = tid & 31;
    float4 hr4 = *(const float4*)(s_hr + l * 4);

    #pragma unroll
    for (int kk = 0; kk < 8; kk++) {
        int k = w * 8 + kk;
        int e = s_eid[k], r = s_rid[k];
        uint2 trb = *(const uint2*)(g_TrTb + (size_t)e * EDIM + l * 4);
        float2 t01 = __bfloat1622float2(*(const __nv_bfloat162*)&trb.x);
        float2 t23 = __bfloat1622float2(*(const __nv_bfloat162*)&trb.y);
        float4 rv = *(const float4*)(g_RelN + (size_t)r * EDIM + l * 4);
        float p = tanh_hw(hr4.x + rv.x) * t01.x + tanh_hw(hr4.y + rv.y) * t01.y +
                  tanh_hw(hr4.z + rv.z) * t23.x + tanh_hw(hr4.w + rv.w) * t23.y;
        #pragma unroll
        for (int o = 16; o; o >>= 1) p += __shfl_xor_sync(0xffffffffu, p, o);
        if (l == 0) s_sc[k] = p;
    }
    __syncthreads();

    if (tid < 32) {
        float sc = s_sc[tid];
        float mx = sc;
        #pragma unroll
        for (int o = 16; o; o >>= 1) mx = fmaxf(mx, __shfl_xor_sync(0xffffffffu, mx, o));
        float ex = __expf(sc - mx);
        float sum = ex;
        #pragma unroll
        for (int o = 16; o; o >>= 1) sum += __shfl_xor_sync(0xffffffffu, sum, o);
        s_att[tid] = ex / sum;
    }
    __syncthreads();

    float acc = 0.f;
    #pragma unroll
    for (int k = 0; k < KNBR; k++)
        acc = fmaf(s_att[k], g_EntN[(size_t)s_eid[k] * EDIM + tid], acc);

    float hv = s_h[tid];
    g_X1[(size_t)b * EDIM + tid] = hv + acc;
    g_X2[(size_t)b * EDIM + tid] = hv * acc;
}

// ---------------- launch ---------------------------------------------------------------
extern "C" void kernel_launch(void* const* d_in, const int* in_sizes, int n_in,
                              void* d_out, int out_size) {
    const int*   idx     = (const int*)d_in[0];
    const int*   adj_ent = (const int*)d_in[1];
    const int*   adj_rel = (const int*)d_in[2];
    const float* ent     = (const float*)d_in[3];
    const float* rel     = (const float*)d_in[4];
    const float* Wr_w    = (const float*)d_in[5];
    const float* Wr_b    = (const float*)d_in[6];
    const float* W1_w    = (const float*)d_in[7];
    const float* W1_b    = (const float*)d_in[8];
    const float* W2_w    = (const float*)d_in[9];
    const float* W2_b    = (const float*)d_in[10];
    float* out = (float*)d_out;

    cudaFuncSetAttribute(k_trt_fused, cudaFuncAttributeMaxDynamicSharedMemorySize, SMEM_TRT);
    cudaFuncSetAttribute(k_gemm_n64<1>, cudaFuncAttributeMaxDynamicSharedMemorySize, SMEM_N64);
    cudaFuncSetAttribute(k_gemm_n64<2>, cudaFuncAttributeMaxDynamicSharedMemorySize, SMEM_N64);

    float *X1, *X2;
    __nv_bfloat16* TrTb;
    cudaGetSymbolAddress((void**)&TrTb, g_TrTb);
    cudaGetSymbolAddress((void**)&X1,   g_X1);
    cudaGetSymbolAddress((void**)&X2,   g_X2);

    k_norm_rel<<<(N_RELS + 7) / 8, 256>>>(rel);
    k_trt_fused<<<(N_ENTS + 127) / 128, 256, SMEM_TRT>>>(ent, Wr_w, Wr_b, TrTb, N_ENTS);
    k_main<<<BATCH, 128>>>(idx, adj_ent, adj_rel);
    dim3 g1(BATCH / 128, 2);
    k_gemm_n64<1><<<g1, 256, SMEM_N64>>>(X1, W1_w, W1_b, out, BATCH);
    k_gemm_n64<2><<<g1, 256, SMEM_N64>>>(X2, W2_w, W2_b, out, BATCH);
}

// round 9
// speedup vs baseline: 1.5238x; 1.0415x over previous
#include <cuda_runtime.h>
#include <cuda_bf16.h>
#include <math.h>
#include <stdint.h>

#define N_ENTS  100000
#define N_RELS  64
#define EDIM    128
#define KNBR    32
#define BATCH   16384

// ---------------- device-global scratch ------------------------------------------
__device__ float         g_EntN[(size_t)N_ENTS * EDIM];   // maxnorm(ent) fp32
__device__ __nv_bfloat16 g_TrTb[(size_t)N_ENTS * EDIM];   // (EntN @ Wr^T + b) bf16
__device__ float         g_RelN[(size_t)N_RELS * EDIM];
__device__ __nv_bfloat16 g_X1h[(size_t)BATCH * EDIM];
__device__ __nv_bfloat16 g_X1l[(size_t)BATCH * EDIM];
__device__ __nv_bfloat16 g_X2h[(size_t)BATCH * EDIM];
__device__ __nv_bfloat16 g_X2l[(size_t)BATCH * EDIM];

// ---------------- helpers ----------------------------------------------------------
__device__ __forceinline__ uint32_t smem_u32(const void* p) {
    uint32_t a;
    asm("{ .reg .u64 t; cvta.to.shared.u64 t, %1; cvt.u32.u64 %0, t; }" : "=r"(a) : "l"(p));
    return a;
}
__device__ __forceinline__ void ldmx4(uint32_t& r0, uint32_t& r1, uint32_t& r2, uint32_t& r3,
                                      uint32_t addr) {
    asm volatile("ldmatrix.sync.aligned.m8n8.x4.shared.b16 {%0,%1,%2,%3}, [%4];"
                 : "=r"(r0), "=r"(r1), "=r"(r2), "=r"(r3) : "r"(addr));
}
__device__ __forceinline__ void mma_bf16(float* d, const uint32_t* a, const uint32_t* b) {
    asm volatile(
        "mma.sync.aligned.m16n8k16.row.col.f32.bf16.bf16.f32 "
        "{%0,%1,%2,%3}, {%4,%5,%6,%7}, {%8,%9}, {%0,%1,%2,%3};"
        : "+f"(d[0]), "+f"(d[1]), "+f"(d[2]), "+f"(d[3])
        : "r"(a[0]), "r"(a[1]), "r"(a[2]), "r"(a[3]), "r"(b[0]), "r"(b[1]));
}
__device__ __forceinline__ uint32_t pk_bf2(__nv_bfloat16 a, __nv_bfloat16 b) {
    __nv_bfloat162 t(a, b);
    return *(uint32_t*)&t;
}
__device__ __forceinline__ float tanh_hw(float x) {
    float y;
    asm("tanh.approx.f32 %0, %1;" : "=f"(y) : "f"(x));
    return y;
}

// padded bf16 tiles, row stride 136 elems (272 B) -> conflict-free ldmatrix
#define LDT 136
#define TILE_B  (128 * LDT * 2)   // 34816
#define HTILE_B (64  * LDT * 2)   // 17408
// TrT kernel layout
#define OFF_BIAS 0
#define OFF_AH   512
#define OFF_BH1  (512 + TILE_B)
#define SMEM_TRT (512 + 2 * TILE_B)              // 70,144 -> 2 CTAs/SM
// fused output kernel layout: bias1|bias2, X1h,X1l,X2h,X2l (128r), W1h,W1l,W2h,W2l (64r)
#define OFF_B1   0
#define OFF_B2   256
#define OA1H     512
#define OA1L     (512 + TILE_B)
#define OA2H     (512 + 2 * TILE_B)
#define OA2L     (512 + 3 * TILE_B)
#define OW1H     (512 + 4 * TILE_B)
#define OW1L     (512 + 4 * TILE_B + HTILE_B)
#define OW2H     (512 + 4 * TILE_B + 2 * HTILE_B)
#define OW2L     (512 + 4 * TILE_B + 3 * HTILE_B)
#define SMEM_OUT (512 + 4 * TILE_B + 4 * HTILE_B)   // 209,408 B -> 1 CTA/SM

// pure bf16 copy: gmem (row stride 128) -> padded smem, 128 rows
__device__ __forceinline__ void copy128(const __nv_bfloat16* __restrict__ src,
                                        char* sm, int off, int tid) {
    #pragma unroll
    for (int i = 0; i < 8; i++) {
        int g = tid + i * 256;
        int row = g >> 4, c8 = g & 15;
        uint4 v = *((const uint4*)(src + (size_t)row * EDIM) + c8);
        *(uint4*)(sm + off + (size_t)row * LDT * 2 + c8 * 16) = v;
    }
}
// fp32 -> bf16 hi/lo split, 64 rows
__device__ __forceinline__ void load_split64(const float* __restrict__ src,
                                             char* sm, int off_h, int off_l, int tid) {
    #pragma unroll
    for (int i = 0; i < 4; i++) {
        int g = tid + i * 256;
        int row = g >> 4, c8 = g & 15, col0 = c8 * 8;
        const float4* p = (const float4*)src + (size_t)row * 32 + c8 * 2;
        float4 v0 = p[0], v1 = p[1];
        float f[8] = {v0.x, v0.y, v0.z, v0.w, v1.x, v1.y, v1.z, v1.w};
        __nv_bfloat16 h[8], l[8];
        #pragma unroll
        for (int j = 0; j < 8; j++) {
            h[j] = __float2bfloat16(f[j]);
            l[j] = __float2bfloat16(f[j] - __bfloat162float(h[j]));
        }
        uint4 hv = make_uint4(pk_bf2(h[0], h[1]), pk_bf2(h[2], h[3]),
                              pk_bf2(h[4], h[5]), pk_bf2(h[6], h[7]));
        uint4 lv = make_uint4(pk_bf2(l[0], l[1]), pk_bf2(l[2], l[3]),
                              pk_bf2(l[4], l[5]), pk_bf2(l[6], l[7]));
        size_t o = (size_t)row * LDT * 2 + col0 * 2;
        *(uint4*)(sm + off_h + o) = hv;
        *(uint4*)(sm + off_l + o) = lv;
    }
}
// hi-only fp32->bf16, 128 rows
__device__ __forceinline__ void load_hi(const float* __restrict__ src,
                                        char* sm, int off_h, int tid) {
    #pragma unroll
    for (int i = 0; i < 8; i++) {
        int g = tid + i * 256;
        int row = g >> 4, c8 = g & 15, col0 = c8 * 8;
        const float4* p = (const float4*)src + (size_t)row * 32 + c8 * 2;
        float4 v0 = p[0], v1 = p[1];
        float f[8] = {v0.x, v0.y, v0.z, v0.w, v1.x, v1.y, v1.z, v1.w};
        __nv_bfloat16 h[8];
        #pragma unroll
        for (int j = 0; j < 8; j++) h[j] = __float2bfloat16(f[j]);
        uint4 hv = make_uint4(pk_bf2(h[0], h[1]), pk_bf2(h[2], h[3]),
                              pk_bf2(h[4], h[5]), pk_bf2(h[6], h[7]));
        *(uint4*)(sm + off_h + (size_t)row * LDT * 2 + col0 * 2) = hv;
    }
}

// ---------- fused maxnorm + single-pass bf16 GEMM -> TrTb (proven) -------------------
__global__ __launch_bounds__(256, 2) void k_trt_fused(const float* __restrict__ ent,
                                                      const float* __restrict__ Wr,
                                                      const float* __restrict__ bias,
                                                      __nv_bfloat16* __restrict__ C,
                                                      int M) {
    extern __shared__ char sm[];
    uint32_t smb = smem_u32(sm);
    int tid  = threadIdx.x;
    int wid  = tid >> 5, lane = tid & 31;
    int wy   = wid >> 2, wx = wid & 3;
    int m0   = blockIdx.x * 128;
    int rows_valid = M - m0;

    if (tid < 128) ((float*)(sm + OFF_BIAS))[tid] = bias[tid];

    #pragma unroll
    for (int i = 0; i < 8; i++) {
        int g = tid + i * 256;
        int row = g >> 4, c8 = g & 15, col0 = c8 * 8;
        float4 v0 = make_float4(0.f, 0.f, 0.f, 0.f), v1 = v0;
        if (row < rows_valid) {
            const float4* p = (const float4*)(ent + (size_t)(m0 + row) * EDIM) + c8 * 2;
            v0 = p[0];
            v1 = p[1];
        }
        float ss = v0.x * v0.x + v0.y * v0.y + v0.z * v0.z + v0.w * v0.w +
                   v1.x * v1.x + v1.y * v1.y + v1.z * v1.z + v1.w * v1.w;
        #pragma unroll
        for (int o = 8; o; o >>= 1) ss += __shfl_xor_sync(0xffffffffu, ss, o);
        float n = sqrtf(ss);
        float s = fminf(1.0f, 1.0f / fmaxf(n, 1e-12f));
        float f[8] = {v0.x * s, v0.y * s, v0.z * s, v0.w * s,
                      v1.x * s, v1.y * s, v1.z * s, v1.w * s};
        if (row < rows_valid) {
            float4* q = (float4*)(g_EntN + (size_t)(m0 + row) * EDIM) + c8 * 2;
            q[0] = make_float4(f[0], f[1], f[2], f[3]);
            q[1] = make_float4(f[4], f[5], f[6], f[7]);
        }
        __nv_bfloat16 h[8];
        #pragma unroll
        for (int j = 0; j < 8; j++) h[j] = __float2bfloat16(f[j]);
        uint4 hv = make_uint4(pk_bf2(h[0], h[1]), pk_bf2(h[2], h[3]),
                              pk_bf2(h[4], h[5]), pk_bf2(h[6], h[7]));
        *(uint4*)(sm + OFF_AH + (size_t)row * LDT * 2 + col0 * 2) = hv;
    }

    load_hi(Wr, sm, OFF_BH1, tid);
    __syncthreads();

    int rowA  = wy * 64 + (lane & 15);
    int colA  = (lane >> 4) * 8;
    int nrow  = wx * 32 + (lane & 7) + ((lane >> 4) ? 8 : 0);
    int kaddB = ((lane >> 3) & 1) * 8;

    uint32_t aB = smb + OFF_AH, bB = smb + OFF_BH1;

    float d[4][4][4];
    #pragma unroll
    for (int i = 0; i < 4; i++)
        #pragma unroll
        for (int j = 0; j < 4; j++)
            #pragma unroll
            for (int q = 0; q < 4; q++) d[i][j][q] = 0.f;

    #pragma unroll
    for (int ks = 0; ks < 8; ks++) {
        int k0 = ks * 16;
        uint32_t a[4][4];
        #pragma unroll
        for (int mi = 0; mi < 4; mi++) {
            uint32_t addr = aB + (uint32_t)(((rowA + mi * 16) * LDT + k0 + colA) * 2);
            ldmx4(a[mi][0], a[mi][1], a[mi][2], a[mi][3], addr);
        }
        uint32_t b[4][2];
        #pragma unroll
        for (int nj2 = 0; nj2 < 2; nj2++) {
            uint32_t addr = bB + (uint32_t)(((nrow + nj2 * 16) * LDT + k0 + kaddB) * 2);
            uint32_t r0, r1, r2, r3;
            ldmx4(r0, r1, r2, r3, addr);
            b[nj2 * 2 + 0][0] = r0; b[nj2 * 2 + 0][1] = r1;
            b[nj2 * 2 + 1][0] = r2; b[nj2 * 2 + 1][1] = r3;
        }
        #pragma unroll
        for (int mi = 0; mi < 4; mi++)
            #pragma unroll
            for (int nj = 0; nj < 4; nj++)
                mma_bf16(d[mi][nj], a[mi], b[nj]);
    }

    const float* sb = (const float*)(sm + OFF_BIAS);
    int qrow = lane >> 2, qcol = (lane & 3) * 2;
    #pragma unroll
    for (int mi = 0; mi < 4; mi++) {
        #pragma unroll
        for (int half = 0; half < 2; half++) {
            int gm = m0 + wy * 64 + mi * 16 + qrow + half * 8;
            if (gm < M) {
                #pragma unroll
                for (int nj = 0; nj < 4; nj++) {
                    int gc = wx * 32 + nj * 8 + qcol;
                    float x0 = d[mi][nj][half * 2 + 0] + sb[gc];
                    float x1 = d[mi][nj][half * 2 + 1] + sb[gc + 1];
                    *(uint32_t*)(C + (size_t)gm * 128 + gc) =
                        pk_bf2(__float2bfloat16(x0), __float2bfloat16(x1));
                }
            }
        }
    }
}

// ------- fused output: out = leaky(X1@W1^T+b1) + leaky(X2@W2^T+b2) -------------------
// CTA tile 128(M) x 64(N), grid (M/128, 2), 1 CTA/SM (209KB smem), both GEMMs per CTA.
// X tiles are pre-split bf16 (pure copy); W tiles split in-kernel (64 rows, cheap).
__global__ __launch_bounds__(256, 1) void k_out_fused(const float* __restrict__ W1,
                                                      const float* __restrict__ b1,
                                                      const float* __restrict__ W2,
                                                      const float* __restrict__ b2,
                                                      float* __restrict__ C, int M) {
    extern __shared__ char sm[];
    uint32_t smb = smem_u32(sm);
    int tid  = threadIdx.x;
    int wid  = tid >> 5, lane = tid & 31;
    int wy   = wid >> 1, wx = wid & 1;          // 4 x 2 warp grid, 32x32 warp tiles
    int m0   = blockIdx.x * 128;
    int n0   = blockIdx.y * 64;

    if (tid < 64) {
        ((float*)(sm + OFF_B1))[tid] = b1[n0 + tid];
        ((float*)(sm + OFF_B2))[tid] = b2[n0 + tid];
    }
    size_t aoff = (size_t)m0 * EDIM;
    copy128(g_X1h + aoff, sm, OA1H, tid);
    copy128(g_X1l + aoff, sm, OA1L, tid);
    copy128(g_X2h + aoff, sm, OA2H, tid);
    copy128(g_X2l + aoff, sm, OA2L, tid);
    load_split64(W1 + (size_t)n0 * EDIM, sm, OW1H, OW1L, tid);
    load_split64(W2 + (size_t)n0 * EDIM, sm, OW2H, OW2L, tid);
    __syncthreads();

    int rowA  = wy * 32 + (lane & 15);
    int colA  = (lane >> 4) * 8;
    int nrow  = wx * 32 + (lane & 7) + ((lane >> 4) ? 8 : 0);
    int kaddB = ((lane >> 3) & 1) * 8;

    float d1[2][4][4], d2[2][4][4];
    #pragma unroll
    for (int i = 0; i < 2; i++)
        #pragma unroll
        for (int j = 0; j < 4; j++)
            #pragma unroll
            for (int q = 0; q < 4; q++) { d1[i][j][q] = 0.f; d2[i][j][q] = 0.f; }

    #pragma unroll
    for (int gemm = 0; gemm < 2; gemm++) {
        uint32_t aH = smb + (gemm ? OA2H : OA1H), aL = smb + (gemm ? OA2L : OA1L);
        uint32_t bH = smb + (gemm ? OW2H : OW1H), bL = smb + (gemm ? OW2L : OW1L);
        float (*d)[4][4] = gemm ? d2 : d1;
        #pragma unroll
        for (int ks = 0; ks < 8; ks++) {
            int k0 = ks * 16;
            #pragma unroll
            for (int pass = 0; pass < 3; pass++) {
                uint32_t aB = (pass == 2) ? aL : aH;
                uint32_t bB = (pass == 1) ? bL : bH;
                uint32_t a[2][4];
                #pragma unroll
                for (int mi = 0; mi < 2; mi++) {
                    uint32_t addr = aB + (uint32_t)(((rowA + mi * 16) * LDT + k0 + colA) * 2);
                    ldmx4(a[mi][0], a[mi][1], a[mi][2], a[mi][3], addr);
                }
                uint32_t b[4][2];
                #pragma unroll
                for (int nj2 = 0; nj2 < 2; nj2++) {
                    uint32_t addr = bB + (uint32_t)(((nrow + nj2 * 16) * LDT + k0 + kaddB) * 2);
                    uint32_t r0, r1, r2, r3;
                    ldmx4(r0, r1, r2, r3, addr);
                    b[nj2 * 2 + 0][0] = r0; b[nj2 * 2 + 0][1] = r1;
                    b[nj2 * 2 + 1][0] = r2; b[nj2 * 2 + 1][1] = r3;
                }
                #pragma unroll
                for (int mi = 0; mi < 2; mi++)
                    #pragma unroll
                    for (int nj = 0; nj < 4; nj++)
                        mma_bf16(d[mi][nj], a[mi], b[nj]);
            }
        }
    }

    const float* sb1 = (const float*)(sm + OFF_B1);
    const float* sb2 = (const float*)(sm + OFF_B2);
    int qrow = lane >> 2, qcol = (lane & 3) * 2;
    #pragma unroll
    for (int mi = 0; mi < 2; mi++) {
        #pragma unroll
        for (int half = 0; half < 2; half++) {
            int gm = m0 + wy * 32 + mi * 16 + qrow + half * 8;
            #pragma unroll
            for (int nj = 0; nj < 4; nj++) {
                int gc = wx * 32 + nj * 8 + qcol;
                float u0 = d1[mi][nj][half * 2 + 0] + sb1[gc];
                float u1 = d1[mi][nj][half * 2 + 1] + sb1[gc + 1];
                float v0 = d2[mi][nj][half * 2 + 0] + sb2[gc];
                float v1 = d2[mi][nj][half * 2 + 1] + sb2[gc + 1];
                u0 = (u0 > 0.f) ? u0 : 0.2f * u0;
                u1 = (u1 > 0.f) ? u1 : 0.2f * u1;
                v0 = (v0 > 0.f) ? v0 : 0.2f * v0;
                v1 = (v1 > 0.f) ? v1 : 0.2f * v1;
                *(float2*)(C + (size_t)gm * 128 + n0 + gc) = make_float2(u0 + v0, u1 + v1);
            }
        }
    }
}

// ---------------- rel-table max-norm (64 rows) ---------------------------------------
__global__ __launch_bounds__(256) void k_norm_rel(const float* __restrict__ rel) {
    int row = blockIdx.x * 8 + (threadIdx.x >> 5);
    int l   = threadIdx.x & 31;
    if (row >= N_RELS) return;
    float4 v = ((const float4*)(rel + (size_t)row * EDIM))[l];
    float ss = v.x * v.x + v.y * v.y + v.z * v.z + v.w * v.w;
    #pragma unroll
    for (int o = 16; o; o >>= 1) ss += __shfl_xor_sync(0xffffffffu, ss, o);
    float n = sqrtf(ss);
    float s = fminf(1.0f, 1.0f / fmaxf(n, 1e-12f));
    ((float4*)(g_RelN + (size_t)row * EDIM))[l] = make_float4(v.x * s, v.y * s, v.z * s, v.w * s);
}

// ---------------- K3: attention + aggregation ----------------------------------------
__global__ __launch_bounds__(128) void k_main(const int* __restrict__ idx,
                                              const int* __restrict__ adj_ent,
                                              const int* __restrict__ adj_rel) {
    __shared__ __align__(16) float s_hr[128];
    __shared__ __align__(16) float s_h[128];
    __shared__ float s_sc[32];
    __shared__ float s_att[32];
    __shared__ int   s_eid[32];
    __shared__ int   s_rid[32];

    int b   = blockIdx.x;
    int tid = threadIdx.x;

    int ib = idx[b];
    ib = min(max(ib, 0), N_ENTS - 1);

    if (tid < 32) {
        int e = adj_ent[(size_t)ib * KNBR + tid];
        s_eid[tid] = min(max(e, 0), N_ENTS - 1);
        int r = adj_rel[(size_t)ib * KNBR + tid];
        s_rid[tid] = min(max(r, 0), N_RELS - 1);
    }
    s_hr[tid] = __bfloat162float(g_TrTb[(size_t)ib * EDIM + tid]);
    s_h[tid]  = g_EntN[(size_t)ib * EDIM + tid];
    __syncthreads();

    int w = tid >> 5, l = tid & 31;
    float4 hr4 = *(const float4*)(s_hr + l * 4);

    #pragma unroll
    for (int kk = 0; kk < 8; kk++) {
        int k = w * 8 + kk;
        int e = s_eid[k], r = s_rid[k];
        uint2 trb = *(const uint2*)(g_TrTb + (size_t)e * EDIM + l * 4);
        float2 t01 = __bfloat1622float2(*(const __nv_bfloat162*)&trb.x);
        float2 t23 = __bfloat1622float2(*(const __nv_bfloat162*)&trb.y);
        float4 rv = *(const float4*)(g_RelN + (size_t)r * EDIM + l * 4);
        float p = tanh_hw(hr4.x + rv.x) * t01.x + tanh_hw(hr4.y + rv.y) * t01.y +
                  tanh_hw(hr4.z + rv.z) * t23.x + tanh_hw(hr4.w + rv.w) * t23.y;
        #pragma unroll
        for (int o = 16; o; o >>= 1) p += __shfl_xor_sync(0xffffffffu, p, o);
        if (l == 0) s_sc[k] = p;
    }
    __syncthreads();

    if (tid < 32) {
        float sc = s_sc[tid];
        float mx = sc;
        #pragma unroll
        for (int o = 16; o; o >>= 1) mx = fmaxf(mx, __shfl_xor_sync(0xffffffffu, mx, o));
        float ex = __expf(sc - mx);
        float sum = ex;
        #pragma unroll
        for (int o = 16; o; o >>= 1) sum += __shfl_xor_sync(0xffffffffu, sum, o);
        s_att[tid] = ex / sum;
    }
    __syncthreads();

    float acc = 0.f;
    #pragma unroll
    for (int k = 0; k < KNBR; k++)
        acc = fmaf(s_att[k], g_EntN[(size_t)s_eid[k] * EDIM + tid], acc);

    float hv = s_h[tid];
    float x1 = hv + acc, x2 = hv * acc;
    size_t o = (size_t)b * EDIM + tid;
    __nv_bfloat16 h1 = __float2bfloat16(x1);
    g_X1h[o] = h1;
    g_X1l[o] = __float2bfloat16(x1 - __bfloat162float(h1));
    __nv_bfloat16 h2 = __float2bfloat16(x2);
    g_X2h[o] = h2;
    g_X2l[o] = __float2bfloat16(x2 - __bfloat162float(h2));
}

// ---------------- launch ---------------------------------------------------------------
extern "C" void kernel_launch(void* const* d_in, const int* in_sizes, int n_in,
                              void* d_out, int out_size) {
    const int*   idx     = (const int*)d_in[0];
    const int*   adj_ent = (const int*)d_in[1];
    const int*   adj_rel = (const int*)d_in[2];
    const float* ent     = (const float*)d_in[3];
    const float* rel     = (const float*)d_in[4];
    const float* Wr_w    = (const float*)d_in[5];
    const float* Wr_b    = (const float*)d_in[6];
    const float* W1_w    = (const float*)d_in[7];
    const float* W1_b    = (const float*)d_in[8];
    const float* W2_w    = (const float*)d_in[9];
    const float* W2_b    = (const float*)d_in[10];
    float* out = (float*)d_out;

    cudaFuncSetAttribute(k_trt_fused, cudaFuncAttributeMaxDynamicSharedMemorySize, SMEM_TRT);
    cudaFuncSetAttribute(k_out_fused, cudaFuncAttributeMaxDynamicSharedMemorySize, SMEM_OUT);

    __nv_bfloat16* TrTb;
    cudaGetSymbolAddress((void**)&TrTb, g_TrTb);

    k_norm_rel<<<(N_RELS + 7) / 8, 256>>>(rel);
    k_trt_fused<<<(N_ENTS + 127) / 128, 256, SMEM_TRT>>>(ent, Wr_w, Wr_b, TrTb, N_ENTS);
    k_main<<<BATCH, 128>>>(idx, adj_ent, adj_rel);
    dim3 go(BATCH / 128, 2);
    k_out_fused<<<go, 256, SMEM_OUT>>>(W1_w, W1_b, W2_w, W2_b, out, BATCH);
}